// round 13
// baseline (speedup 1.0000x reference)
#include <cuda_runtime.h>
#include <cuda_bf16.h>
#include <cstdint>

#define NMAX 32768
#define EMAX 524288

// ---------------- scratch (static device globals; no allocation) ----------------
__device__ float g_U [NMAX * 128];
__device__ float g_A [NMAX * 128];
__device__ float g_B [NMAX * 128];
__device__ uint32_t g_HI[NMAX * 128];   // interleaved H: [row][pair]{hi,lo} uint32
__device__ uint32_t g_XI[NMAX * 64];    // interleaved X (64-dim): [row][pair]{hi,lo}
__device__ __nv_bfloat16 g_Whi[6 * 128 * 128];
__device__ __nv_bfloat16 g_Wlo[6 * 128 * 128];
__device__ float g_inv[NMAX];
__device__ int   g_rs [NMAX + 1];
__device__ int   g_csr[EMAX];
__device__ float g_G  [64 * 128];

// ---- fused CSR build + prescale + weight conversion (blockIdx branch) -----------
__global__ void __launch_bounds__(512)
k_csrw(const int* __restrict__ ei, const float* __restrict__ x,
       float* __restrict__ xs, int E, int n_per, int e_per, int B,
       const float* w0, const float* w1, const float* w2,
       const float* w3, const float* w4, const float* w5) {
    int blk = blockIdx.x, tid = threadIdx.x;
    if (blk >= B) {
        int b = blk - B;
        const float* srcs[6] = {w0, w1, w2, w3, w4, w5};
        const int Ks[6] = {64, 128, 128, 128, 128, 128};
        const float* W = srcs[b];
        int K = Ks[b];
        __nv_bfloat16* oh = g_Whi + b * 16384;
        __nv_bfloat16* ol = g_Wlo + b * 16384;
        for (int id = tid; id < 128 * K; id += 512) {
            int n = id / K, k = id % K;
            float v = W[k * 128 + n];             // transpose: Wt[n,k] = W[k,n]
            __nv_bfloat16 h = __float2bfloat16(v);
            oh[id] = h;
            ol[id] = __float2bfloat16(v - __bfloat162float(h));
        }
        return;
    }
    __shared__ int cnt[512];
    __shared__ int off[512];
    __shared__ float sinv[512];
    int g = blk;
    int node0 = g * n_per;
    int ebase = g * e_per;
    cnt[tid] = 0;
    __syncthreads();
    for (int j = tid; j < e_per; j += 512)
        atomicAdd(&cnt[ei[E + ebase + j] - node0], 1);
    __syncthreads();
    int v = cnt[tid];
    off[tid] = v;
    __syncthreads();
#pragma unroll
    for (int s = 1; s < 512; s <<= 1) {
        int t = (tid >= s) ? off[tid - s] : 0;
        __syncthreads();
        off[tid] += t;
        __syncthreads();
    }
    int excl = off[tid] - v;
    float iv = rsqrtf((float)(v + 1));
    g_rs[node0 + tid] = ebase + excl;
    g_inv[node0 + tid] = iv;
    sinv[tid] = iv;
    if (tid == 511) g_rs[node0 + 512] = ebase + e_per;
    cnt[tid] = ebase + excl;
    __syncthreads();
    for (int j = tid; j < e_per; j += 512) {
        int src = ei[ebase + j];
        int ld  = ei[E + ebase + j] - node0;
        int pos = atomicAdd(&cnt[ld], 1);
        g_csr[pos] = src;
    }
    const float2* xg = (const float2*)x;
    float2* xo = (float2*)xs;
    size_t base2 = (size_t)node0 * 32;
    for (int i = tid; i < n_per * 32; i += 512) {
        int row = i >> 5;
        float2 vv = xg[base2 + i];
        float s = sinv[row];
        vv.x *= s; vv.y *= s;
        xo[base2 + i] = vv;
    }
}

// ---- pack helper: two fp32 -> interleaved {hi_u32, lo_u32} -----------------------
__device__ __forceinline__ uint2 pack_hilo(float a, float b) {
    __nv_bfloat16 ha = __float2bfloat16(a), hb = __float2bfloat16(b);
    __nv_bfloat162 hi; hi.x = ha; hi.y = hb;
    __nv_bfloat162 lo;
    lo.x = __float2bfloat16(a - __bfloat162float(ha));
    lo.y = __float2bfloat16(b - __bfloat162float(hb));
    uint2 r;
    r.x = *(uint32_t*)&hi;
    r.y = *(uint32_t*)&lo;
    return r;
}

// ---- layer-1 gather: block per graph, warp per node, lane = 2 dims ---------------
__global__ void __launch_bounds__(512)
k_gather64s(const float* __restrict__ xs, uint32_t* __restrict__ XI, int n_per) {
    extern __shared__ float sU[];                 // [512][66]
    int g = blockIdx.x;
    int tid = threadIdx.x, wid = tid >> 5, lane = tid & 31;
    int node0 = g * n_per;

    for (int i = tid; i < n_per * 32; i += 512) {
        int row = i >> 5, l = i & 31;
        ((float2*)sU)[row * 33 + l] = *(const float2*)(xs + (size_t)(node0 + row) * 64 + 2 * l);
    }
    __syncthreads();

    const float2* sU2 = (const float2*)sU;
    for (int nn = wid; nn < n_per; nn += 16) {
        float2 acc = sU2[nn * 33 + lane];
        float2 acc2 = make_float2(0.f, 0.f);
        int s = g_rs[node0 + nn], e = g_rs[node0 + nn + 1], j = s;
        for (; j + 1 < e; j += 2) {
            int a = g_csr[j] - node0, b = g_csr[j + 1] - node0;
            float2 v0 = sU2[a * 33 + lane], v1 = sU2[b * 33 + lane];
            acc.x += v0.x; acc.y += v0.y;
            acc2.x += v1.x; acc2.y += v1.y;
        }
        if (j < e) {
            float2 v0 = sU2[(g_csr[j] - node0) * 33 + lane];
            acc.x += v0.x; acc.y += v0.y;
        }
        float iv = g_inv[node0 + nn];
        float ox = (acc.x + acc2.x) * iv, oy = (acc.y + acc2.y) * iv;
        ((uint2*)XI)[(size_t)(node0 + nn) * 32 + lane] = pack_hilo(ox, oy);
    }
}

// ---------------- mma helper ----------------
#define MMA16816(c, a, b0, b1)                                             \
    asm volatile("mma.sync.aligned.m16n8k16.row.col.f32.bf16.bf16.f32 "    \
        "{%0,%1,%2,%3}, {%4,%5,%6,%7}, {%8,%9}, {%0,%1,%2,%3};"            \
        : "+f"((c)[0]), "+f"((c)[1]), "+f"((c)[2]), "+f"((c)[3])           \
        : "r"((a)[0]), "r"((a)[1]), "r"((a)[2]), "r"((a)[3]),              \
          "r"(b0), "r"(b1))

// smem B layout: sBI as uint2[pair][132], pair-row stride 132 8B units (132%16==4)
#define NST8 132

// ---- full-width GEMM, interleaved operands: CTA 128M x 128N, warp m32 x n64 ------
// MODE 0: Y = inv[row]*acc (fp32)   MODE 3: relu(acc+bias) -> interleaved HI
template <int K, int MODE>
__global__ void __launch_bounds__(256)
k_gemm_mma(const uint32_t* __restrict__ XI,
           const __nv_bfloat16* __restrict__ Whi, const __nv_bfloat16* __restrict__ Wlo,
           const float* __restrict__ bias, float* __restrict__ Y,
           uint32_t* __restrict__ HI) {
    extern __shared__ uint32_t sBI[];               // uint2[K/2][NST8]
    uint2* sB2 = (uint2*)sBI;

    int tid = threadIdx.x, wid = tid >> 5, lane = tid & 31;
    int q = lane & 3, g4 = lane >> 2;
    int m0 = blockIdx.x * 128 + (wid & 3) * 32;
    int nh = wid >> 2;

    for (int id = tid; id < 128 * (K / 2); id += 256) {
        int p = id % (K / 2), n = id / (K / 2);
        uint2 w;
        w.x = *(const uint32_t*)(Whi + (size_t)n * K + 2 * p);
        w.y = *(const uint32_t*)(Wlo + (size_t)n * K + 2 * p);
        sB2[p * NST8 + n] = w;
    }
    __syncthreads();

    float c[2][8][4] = {};
    for (int kc = 0; kc < K / 16; kc++) {
        int pb = kc * 8 + q;
        uint32_t ah[2][4], al[2][4];
#pragma unroll
        for (int mh = 0; mh < 2; mh++) {
            const uint2* xr0 = (const uint2*)(XI + (size_t)(m0 + mh * 16 + g4) * K);
            const uint2* xr1 = (const uint2*)(XI + (size_t)(m0 + mh * 16 + g4 + 8) * K);
            uint2 v0 = xr0[pb];
            uint2 v1 = xr1[pb];
            uint2 v2 = xr0[pb + 4];
            uint2 v3 = xr1[pb + 4];
            ah[mh][0] = v0.x; al[mh][0] = v0.y;
            ah[mh][1] = v1.x; al[mh][1] = v1.y;
            ah[mh][2] = v2.x; al[mh][2] = v2.y;
            ah[mh][3] = v3.x; al[mh][3] = v3.y;
        }
#pragma unroll
        for (int nc = 0; nc < 8; nc++) {
            int n = nh * 64 + nc * 8 + g4;
            uint2 b0 = sB2[pb * NST8 + n];
            uint2 b1 = sB2[(pb + 4) * NST8 + n];
#pragma unroll
            for (int mh = 0; mh < 2; mh++) {
                MMA16816(c[mh][nc], ah[mh], b0.x, b1.x);
                MMA16816(c[mh][nc], ah[mh], b0.y, b1.y);
                MMA16816(c[mh][nc], al[mh], b0.x, b1.x);
            }
        }
    }

#pragma unroll
    for (int mh = 0; mh < 2; mh++) {
        int r0 = m0 + mh * 16 + g4;
        if (MODE == 0) {
            float s0 = g_inv[r0], s1 = g_inv[r0 + 8];
#pragma unroll
            for (int nc = 0; nc < 8; nc++) {
                int col = nh * 64 + nc * 8 + q * 2;
                *(float2*)(Y + (size_t)r0 * 128 + col) =
                    make_float2(c[mh][nc][0] * s0, c[mh][nc][1] * s0);
                *(float2*)(Y + (size_t)(r0 + 8) * 128 + col) =
                    make_float2(c[mh][nc][2] * s1, c[mh][nc][3] * s1);
            }
        } else {
#pragma unroll
            for (int nc = 0; nc < 8; nc++) {
                int col = nh * 64 + nc * 8 + q * 2;
                float b0 = __ldg(bias + col), b1 = __ldg(bias + col + 1);
                float t0 = fmaxf(c[mh][nc][0] + b0, 0.f);
                float t1 = fmaxf(c[mh][nc][1] + b1, 0.f);
                float t2 = fmaxf(c[mh][nc][2] + b0, 0.f);
                float t3 = fmaxf(c[mh][nc][3] + b1, 0.f);
                ((uint2*)HI)[(size_t)r0 * 64 + col / 2] = pack_hilo(t0, t1);
                ((uint2*)HI)[(size_t)(r0 + 8) * 64 + col / 2] = pack_hilo(t2, t3);
            }
        }
    }
}

// ---- heads GEMM: grid = 3*gg. p=0 fused node head -> out; p=1/2 store A/Bm ------
__global__ void __launch_bounds__(256)
k_heads(const uint32_t* __restrict__ XI,
        const float* __restrict__ bn1, const float* __restrict__ wn2,
        const float* __restrict__ bn2, float* __restrict__ out, int MA,
        float* __restrict__ Ya, float* __restrict__ Yb, int gg) {
    constexpr int K = 128;
    extern __shared__ uint32_t sBI[];
    uint2* sB2 = (uint2*)sBI;
    __shared__ float slg[2][128][4];

    int p = blockIdx.x / gg;                       // 0: node head, 1: A, 2: Bm
    int mb = blockIdx.x - p * gg;
    const __nv_bfloat16* Whi = g_Whi + (3 + p) * 16384;
    const __nv_bfloat16* Wlo = g_Wlo + (3 + p) * 16384;

    int tid = threadIdx.x, wid = tid >> 5, lane = tid & 31;
    int q = lane & 3, g4 = lane >> 2;
    int m0 = mb * 128 + (wid & 3) * 32;
    int nh = wid >> 2;

    for (int id = tid; id < 128 * (K / 2); id += 256) {
        int pp = id % (K / 2), n = id / (K / 2);
        uint2 w;
        w.x = *(const uint32_t*)(Whi + (size_t)n * K + 2 * pp);
        w.y = *(const uint32_t*)(Wlo + (size_t)n * K + 2 * pp);
        sB2[pp * NST8 + n] = w;
    }
    __syncthreads();

    float c[2][8][4] = {};
    for (int kc = 0; kc < K / 16; kc++) {
        int pb = kc * 8 + q;
        uint32_t ah[2][4], al[2][4];
#pragma unroll
        for (int mh = 0; mh < 2; mh++) {
            const uint2* xr0 = (const uint2*)(XI + (size_t)(m0 + mh * 16 + g4) * K);
            const uint2* xr1 = (const uint2*)(XI + (size_t)(m0 + mh * 16 + g4 + 8) * K);
            uint2 v0 = xr0[pb];
            uint2 v1 = xr1[pb];
            uint2 v2 = xr0[pb + 4];
            uint2 v3 = xr1[pb + 4];
            ah[mh][0] = v0.x; al[mh][0] = v0.y;
            ah[mh][1] = v1.x; al[mh][1] = v1.y;
            ah[mh][2] = v2.x; al[mh][2] = v2.y;
            ah[mh][3] = v3.x; al[mh][3] = v3.y;
        }
#pragma unroll
        for (int nc = 0; nc < 8; nc++) {
            int n = nh * 64 + nc * 8 + g4;
            uint2 b0 = sB2[pb * NST8 + n];
            uint2 b1 = sB2[(pb + 4) * NST8 + n];
#pragma unroll
            for (int mh = 0; mh < 2; mh++) {
                MMA16816(c[mh][nc], ah[mh], b0.x, b1.x);
                MMA16816(c[mh][nc], ah[mh], b0.y, b1.y);
                MMA16816(c[mh][nc], al[mh], b0.x, b1.x);
            }
        }
    }

    if (p != 0) {
        float* Y = (p == 1) ? Ya : Yb;
#pragma unroll
        for (int mh = 0; mh < 2; mh++) {
            int r0 = m0 + mh * 16 + g4;
#pragma unroll
            for (int nc = 0; nc < 8; nc++) {
                int col = nh * 64 + nc * 8 + q * 2;
                *(float2*)(Y + (size_t)r0 * 128 + col) =
                    make_float2(c[mh][nc][0], c[mh][nc][1]);
                *(float2*)(Y + (size_t)(r0 + 8) * 128 + col) =
                    make_float2(c[mh][nc][2], c[mh][nc][3]);
            }
        }
        return;
    }
    float lg[4][4] = {};
#pragma unroll
    for (int mh = 0; mh < 2; mh++) {
#pragma unroll
        for (int nc = 0; nc < 8; nc++) {
            int col = nh * 64 + nc * 8 + q * 2;
            float b0 = __ldg(bn1 + col), b1 = __ldg(bn1 + col + 1);
            float4 w0 = __ldg((const float4*)wn2 + col);
            float4 w1 = __ldg((const float4*)wn2 + col + 1);
            float t0 = fmaxf(c[mh][nc][0] + b0, 0.f);
            float t1 = fmaxf(c[mh][nc][1] + b1, 0.f);
            float t2 = fmaxf(c[mh][nc][2] + b0, 0.f);
            float t3 = fmaxf(c[mh][nc][3] + b1, 0.f);
            int ra = mh * 2, rb = mh * 2 + 1;
            lg[ra][0] += t0 * w0.x + t1 * w1.x;
            lg[ra][1] += t0 * w0.y + t1 * w1.y;
            lg[ra][2] += t0 * w0.z + t1 * w1.z;
            lg[ra][3] += t0 * w0.w + t1 * w1.w;
            lg[rb][0] += t2 * w0.x + t3 * w1.x;
            lg[rb][1] += t2 * w0.y + t3 * w1.y;
            lg[rb][2] += t2 * w0.z + t3 * w1.z;
            lg[rb][3] += t2 * w0.w + t3 * w1.w;
        }
    }
#pragma unroll
    for (int i = 0; i < 4; i++)
#pragma unroll
        for (int a = 0; a < 4; a++) {
            lg[i][a] += __shfl_xor_sync(0xffffffffu, lg[i][a], 1);
            lg[i][a] += __shfl_xor_sync(0xffffffffu, lg[i][a], 2);
        }
    if (q == 0) {
        int lr0 = (wid & 3) * 32 + g4;
#pragma unroll
        for (int i = 0; i < 4; i++) {
            int lr = lr0 + ((i & 1) ? 8 : 0) + ((i >> 1) ? 16 : 0);
#pragma unroll
            for (int a = 0; a < 4; a++) slg[nh][lr][a] = lg[i][a];
        }
    }
    __syncthreads();
    for (int id = tid; id < 512; id += 256) {
        int lr = id >> 2, a = id & 3;
        int R = mb * 128 + lr;
        int g = R >> 9, ln = R & 511;
        out[(size_t)g * MA + ln * 4 + a] =
            slg[0][lr][a] + slg[1][lr][a] + __ldg(bn2 + a);
    }
}

// ---- GCN aggregation (layers 2/3): block=(g, half of 64 dims), lane = 2 dims -----
__global__ void __launch_bounds__(512)
k_gatherq(const float* __restrict__ U, const float* __restrict__ bias,
          uint32_t* __restrict__ HI, int n_per, float* __restrict__ Gout) {
    extern __shared__ float sU[];                 // [512][66]
    __shared__ float spool[16][66];
    int b = blockIdx.x;
    int g = b >> 1, hh = b & 1;
    int qd = hh * 64;
    int tid = threadIdx.x, wid = tid >> 5, lane = tid & 31;
    int node0 = g * n_per;

    for (int i = tid; i < n_per * 32; i += 512) {
        int row = i >> 5, l = i & 31;
        ((float2*)sU)[row * 33 + l] =
            *(const float2*)(U + (size_t)(node0 + row) * 128 + qd + 2 * l);
    }
    __syncthreads();

    const float2* sU2 = (const float2*)sU;
    float2 bb = *(const float2*)(bias + qd + 2 * lane);
    float px = 0.f, py = 0.f;
    for (int nn = wid; nn < n_per; nn += 16) {
        float2 acc = sU2[nn * 33 + lane];
        float2 acc2 = make_float2(0.f, 0.f);
        int s = g_rs[node0 + nn], e = g_rs[node0 + nn + 1], j = s;
        for (; j + 1 < e; j += 2) {
            int a = g_csr[j] - node0, bn = g_csr[j + 1] - node0;
            float2 v0 = sU2[a * 33 + lane], v1 = sU2[bn * 33 + lane];
            acc.x += v0.x; acc.y += v0.y;
            acc2.x += v1.x; acc2.y += v1.y;
        }
        if (j < e) {
            float2 v0 = sU2[(g_csr[j] - node0) * 33 + lane];
            acc.x += v0.x; acc.y += v0.y;
        }
        float iv = g_inv[node0 + nn];
        float ox = fmaxf(fmaf(acc.x + acc2.x, iv, bb.x), 0.f);
        float oy = fmaxf(fmaf(acc.y + acc2.y, iv, bb.y), 0.f);
        px += ox; py += oy;
        ((uint2*)HI)[(size_t)(node0 + nn) * 64 + qd / 2 + lane] = pack_hilo(ox, oy);
    }
    if (Gout != nullptr) {
        spool[wid][2 * lane] = px;
        spool[wid][2 * lane + 1] = py;
        __syncthreads();
        if (tid < 64) {
            float s = 0.f;
#pragma unroll
            for (int w = 0; w < 16; w++) s += spool[w][tid];
            Gout[g * 128 + qd + tid] = s / (float)n_per;
        }
    }
}

// ---- edge head + value head merged (unchanged from R12) -------------------------
#define EQ_STRIDE 36
__global__ void __launch_bounds__(512)
k_edgev(const float* __restrict__ A, const float* __restrict__ Bm,
        const int* __restrict__ ei, const float* __restrict__ be1,
        const float* __restrict__ we2, const float* __restrict__ be2,
        float* __restrict__ out, int E, int n_per, int e_per, int MA, int nblk,
        int B, const float* __restrict__ wv1, const float* __restrict__ bv1,
        const float* __restrict__ wv2, const float* __restrict__ bv2, int voff) {
    extern __shared__ float sm[];
    int b = blockIdx.x;
    int tid = threadIdx.x;
    if (b >= 2 * B) {
        int g = b - 2 * B;
        float* gs  = sm;
        float* red = sm + 128;
        if (tid < 128) gs[tid] = g_G[g * 128 + tid];
        __syncthreads();
        if (tid < 128) {
            float acc = bv1[tid];
#pragma unroll
            for (int k = 0; k < 128; k++) acc = fmaf(gs[k], wv1[k * 128 + tid], acc);
            red[tid] = fmaxf(acc, 0.f) * wv2[tid];
        }
        __syncthreads();
        for (int off = 64; off; off >>= 1) {
            if (tid < off) red[tid] += red[tid + off];
            __syncthreads();
        }
        if (tid == 0) out[voff + g] = red[0] + bv2[0];
        return;
    }
    float* sA = sm;
    float* sB = sm + n_per * EQ_STRIDE;
    __shared__ float swb[32][4];
    int g = b >> 1, eh = b & 1;
    int node0 = g * n_per;
    int ehalf = e_per >> 1;
    int e0 = g * e_per + eh * ehalf;

    int srcs[8], dsts[8];
#pragma unroll
    for (int j = 0; j < 8; j++) {
        int ge = e0 + tid + j * 512;
        srcs[j] = (ei[ge] - node0) * EQ_STRIDE;
        dsts[j] = (ei[E + ge] - node0) * EQ_STRIDE;
    }
    float p0[8], p1[8];
#pragma unroll
    for (int j = 0; j < 8; j++) { p0[j] = 0.f; p1[j] = 0.f; }

    for (int q = 0; q < 4; q++) {
        int qd = q * 32;
        __syncthreads();
        for (int i = tid; i < n_per * 8; i += 512) {
            int row = i >> 3, c = (i & 7) << 2;
            *(float4*)&sA[row * EQ_STRIDE + c] =
                *(const float4*)(A + (size_t)(node0 + row) * 128 + qd + c);
            *(float4*)&sB[row * EQ_STRIDE + c] =
                *(const float4*)(Bm + (size_t)(node0 + row) * 128 + qd + c);
        }
        if (tid < 32) {
            swb[tid][0] = we2[(qd + tid) * 2];
            swb[tid][1] = we2[(qd + tid) * 2 + 1];
            swb[tid][2] = be1[qd + tid];
        }
        __syncthreads();
#pragma unroll
        for (int j = 0; j < 8; j++) {
            int s = srcs[j], dd = dsts[j];
            float a0 = p0[j], a1 = p1[j];
#pragma unroll
            for (int d = 0; d < 32; d += 4) {
                float4 a4 = *(const float4*)&sA[s + d];
                float4 b4 = *(const float4*)&sB[dd + d];
                float t;
                t = fmaxf(a4.x + b4.x + swb[d][2], 0.f);
                a0 += t * swb[d][0]; a1 += t * swb[d][1];
                t = fmaxf(a4.y + b4.y + swb[d + 1][2], 0.f);
                a0 += t * swb[d + 1][0]; a1 += t * swb[d + 1][1];
                t = fmaxf(a4.z + b4.z + swb[d + 2][2], 0.f);
                a0 += t * swb[d + 2][0]; a1 += t * swb[d + 2][1];
                t = fmaxf(a4.w + b4.w + swb[d + 3][2], 0.f);
                a0 += t * swb[d + 3][0]; a1 += t * swb[d + 3][1];
            }
            p0[j] = a0; p1[j] = a1;
        }
    }
    float bb0 = __ldg(be2), bb1 = __ldg(be2 + 1);
    size_t obase = (size_t)g * MA + nblk;
    int le0 = eh * ehalf;
#pragma unroll
    for (int j = 0; j < 8; j++) {
        int le = le0 + tid + j * 512;
        *(float2*)&out[obase + (size_t)le * 2] = make_float2(p0[j] + bb0, p1[j] + bb1);
    }
}

// ---------------- launch ----------------
extern "C" void kernel_launch(void* const* d_in, const int* in_sizes, int n_in,
                              void* d_out, int out_size) {
    const float* x  = (const float*)d_in[0];
    const int*   ei = (const int*)d_in[1];
    int N = in_sizes[0] / 64;
    int E = in_sizes[1] / 2;

    int wb = n_in - 18;
    const float* w_g1 = (const float*)d_in[wb + 0];
    const float* b_g1 = (const float*)d_in[wb + 1];
    const float* w_g2 = (const float*)d_in[wb + 2];
    const float* b_g2 = (const float*)d_in[wb + 3];
    const float* w_g3 = (const float*)d_in[wb + 4];
    const float* b_g3 = (const float*)d_in[wb + 5];
    const float* wn1  = (const float*)d_in[wb + 6];
    const float* bn1  = (const float*)d_in[wb + 7];
    const float* wn2  = (const float*)d_in[wb + 8];
    const float* bn2  = (const float*)d_in[wb + 9];
    const float* we1  = (const float*)d_in[wb + 10];
    const float* be1  = (const float*)d_in[wb + 11];
    const float* we2  = (const float*)d_in[wb + 12];
    const float* be2  = (const float*)d_in[wb + 13];
    const float* wv1  = (const float*)d_in[wb + 14];
    const float* bv1  = (const float*)d_in[wb + 15];
    const float* wv2  = (const float*)d_in[wb + 16];
    const float* bv2  = (const float*)d_in[wb + 17];

    const int n_per = 512;
    int B     = N / n_per;
    int e_per = E / B;
    int MA    = n_per * 4 + e_per * 2;
    int voff  = out_size - B;
    float* out = (float*)d_out;

    float *U, *A, *Bm, *G;
    uint32_t *HI, *XI;
    __nv_bfloat16 *Whi, *Wlo;
    cudaGetSymbolAddress((void**)&U,   g_U);
    cudaGetSymbolAddress((void**)&A,   g_A);
    cudaGetSymbolAddress((void**)&Bm,  g_B);
    cudaGetSymbolAddress((void**)&G,   g_G);
    cudaGetSymbolAddress((void**)&HI,  g_HI);
    cudaGetSymbolAddress((void**)&XI,  g_XI);
    cudaGetSymbolAddress((void**)&Whi, g_Whi);
    cudaGetSymbolAddress((void**)&Wlo, g_Wlo);

    const int SMB64  = 32 * NST8 * 8;              // 33,792 B
    const int SMB128 = 64 * NST8 * 8;              // 67,584 B
    const int SMEQ   = n_per * EQ_STRIDE * 4 * 2;  // 147,456 B
    const int SMGF   = n_per * 66 * 4;             // 135,168 B
    cudaFuncSetAttribute(k_gemm_mma<64, 3>,  cudaFuncAttributeMaxDynamicSharedMemorySize, SMB64);
    cudaFuncSetAttribute(k_gemm_mma<128, 0>, cudaFuncAttributeMaxDynamicSharedMemorySize, SMB128);
    cudaFuncSetAttribute(k_heads,            cudaFuncAttributeMaxDynamicSharedMemorySize, SMB128);
    cudaFuncSetAttribute(k_edgev,            cudaFuncAttributeMaxDynamicSharedMemorySize, SMEQ);
    cudaFuncSetAttribute(k_gatherq,          cudaFuncAttributeMaxDynamicSharedMemorySize, SMGF);
    cudaFuncSetAttribute(k_gather64s,        cudaFuncAttributeMaxDynamicSharedMemorySize, SMGF);

    int gg = N / 128;

    // (1) fused CSR build + prescale + weight conversion
    k_csrw<<<B + 6, 512>>>(ei, x, U, E, n_per, e_per, B,
                           w_g1, w_g2, w_g3, wn1, we1, we1 + 128 * 128);
    // (2) layer-1 aggregate-first gather -> interleaved XI
    k_gather64s<<<B, 512, SMGF>>>(U, XI, n_per);
    // (3) layer-1 GEMM -> interleaved HI
    k_gemm_mma<64, 3><<<gg, 256, SMB64>>>(XI, Whi + 0 * 16384, Wlo + 0 * 16384,
                                          b_g1, nullptr, HI);
    // layer 2
    k_gemm_mma<128, 0><<<gg, 256, SMB128>>>(HI, Whi + 1 * 16384, Wlo + 1 * 16384,
                                            nullptr, U, nullptr);
    k_gatherq<<<B * 2, 512, SMGF>>>(U, b_g2, HI, n_per, nullptr);
    // layer 3 (+ fused mean pool)
    k_gemm_mma<128, 0><<<gg, 256, SMB128>>>(HI, Whi + 2 * 16384, Wlo + 2 * 16384,
                                            nullptr, U, nullptr);
    k_gatherq<<<B * 2, 512, SMGF>>>(U, b_g3, HI, n_per, G);

    // heads: node (fused) + edge A + edge Bm in one launch
    k_heads<<<3 * gg, 256, SMB128>>>(HI, bn1, wn2, bn2, out, MA, A, Bm, gg);

    // edge head + value head in one launch
    k_edgev<<<B * 2 + B, 512, SMEQ>>>(A, Bm, ei, be1, we2, be2, out,
                                      E, n_per, e_per, MA, n_per * 4,
                                      B, wv1, bv1, wv2, bv2, voff);
}

// round 15
// speedup vs baseline: 1.0443x; 1.0443x over previous
#include <cuda_runtime.h>
#include <cuda_bf16.h>
#include <cstdint>

#define NMAX 32768
#define EMAX 524288

// ---------------- scratch (static device globals; no allocation) ----------------
__device__ float g_U [NMAX * 128];
__device__ float g_A [NMAX * 128];
__device__ float g_B [NMAX * 128];
__device__ __nv_bfloat16 g_Hhi[NMAX * 128];
__device__ __nv_bfloat16 g_Hlo[NMAX * 128];
__device__ __nv_bfloat16 g_Xhi[NMAX * 64];
__device__ __nv_bfloat16 g_Xlo[NMAX * 64];
__device__ __nv_bfloat16 g_Whi[6 * 128 * 128];
__device__ __nv_bfloat16 g_Wlo[6 * 128 * 128];
__device__ float g_inv[NMAX];
__device__ int   g_rs [NMAX + 1];
__device__ int   g_csr[EMAX];
__device__ float g_G  [64 * 128];

// ---- fused: CSR build + prescale(into smem) + layer-1 gather + weight conv ------
// blocks 0..B-1: per-graph CSR/scan/fill, stage xs=x*inv in smem, then gather
//                x~ = inv*(sum_in xs + xs_self) -> bf16 hi/lo (Xhi/Xlo).
// blocks B..B+5: weight conversion (transpose + bf16 hi/lo split).
__global__ void __launch_bounds__(512)
k_csrg(const int* __restrict__ ei, const float* __restrict__ x,
       __nv_bfloat16* __restrict__ Xhi, __nv_bfloat16* __restrict__ Xlo,
       int E, int n_per, int e_per, int B,
       const float* w0, const float* w1, const float* w2,
       const float* w3, const float* w4, const float* w5) {
    int blk = blockIdx.x, tid = threadIdx.x;
    if (blk >= B) {
        int b = blk - B;
        const float* srcs[6] = {w0, w1, w2, w3, w4, w5};
        const int Ks[6] = {64, 128, 128, 128, 128, 128};
        const float* W = srcs[b];
        int K = Ks[b];
        __nv_bfloat16* oh = g_Whi + b * 16384;
        __nv_bfloat16* ol = g_Wlo + b * 16384;
        for (int id = tid; id < 128 * K; id += 512) {
            int n = id / K, k = id % K;
            float v = W[k * 128 + n];             // transpose: Wt[n,k] = W[k,n]
            __nv_bfloat16 h = __float2bfloat16(v);
            oh[id] = h;
            ol[id] = __float2bfloat16(v - __bfloat162float(h));
        }
        return;
    }
    extern __shared__ float sU[];                 // [512][66] staged xs
    __shared__ int cnt[512];
    __shared__ int off[512];
    __shared__ float sinv[512];
    int g = blk;
    int node0 = g * n_per;
    int ebase = g * e_per;
    int wid = tid >> 5, lane = tid & 31;

    cnt[tid] = 0;
    __syncthreads();
    for (int j = tid; j < e_per; j += 512)
        atomicAdd(&cnt[ei[E + ebase + j] - node0], 1);
    __syncthreads();
    int v = cnt[tid];
    off[tid] = v;
    __syncthreads();
#pragma unroll
    for (int s = 1; s < 512; s <<= 1) {
        int t = (tid >= s) ? off[tid - s] : 0;
        __syncthreads();
        off[tid] += t;
        __syncthreads();
    }
    int excl = off[tid] - v;
    float iv = rsqrtf((float)(v + 1));
    g_rs[node0 + tid] = ebase + excl;
    g_inv[node0 + tid] = iv;
    sinv[tid] = iv;
    if (tid == 511) g_rs[node0 + 512] = ebase + e_per;
    cnt[tid] = ebase + excl;                      // reuse as global cursor
    __syncthreads();
    for (int j = tid; j < e_per; j += 512) {
        int src = ei[ebase + j];
        int ld  = ei[E + ebase + j] - node0;
        int pos = atomicAdd(&cnt[ld], 1);
        g_csr[pos] = src;
    }
    // prescale into smem: sU[row][2l..2l+1] = x[row] * inv[row]
    const float2* xg = (const float2*)x;
    size_t base2 = (size_t)node0 * 32;
    for (int i = tid; i < n_per * 32; i += 512) {
        int row = i >> 5, l = i & 31;
        float2 vv = xg[base2 + i];
        float s = sinv[row];
        vv.x *= s; vv.y *= s;
        ((float2*)sU)[row * 33 + l] = vv;
    }
    __syncthreads();                              // csr(global) + sU visible

    // layer-1 gather: warp per node, lane = 2 dims
    const float2* sU2 = (const float2*)sU;
    for (int nn = wid; nn < n_per; nn += 16) {
        float2 acc = sU2[nn * 33 + lane];         // self loop
        float2 acc2 = make_float2(0.f, 0.f);
        int s = g_rs[node0 + nn], e = g_rs[node0 + nn + 1], j = s;
        for (; j + 1 < e; j += 2) {
            int a = g_csr[j] - node0, b2 = g_csr[j + 1] - node0;
            float2 v0 = sU2[a * 33 + lane], v1 = sU2[b2 * 33 + lane];
            acc.x += v0.x; acc.y += v0.y;
            acc2.x += v1.x; acc2.y += v1.y;
        }
        if (j < e) {
            float2 v0 = sU2[(g_csr[j] - node0) * 33 + lane];
            acc.x += v0.x; acc.y += v0.y;
        }
        float ivn = sinv[nn];
        float ox = (acc.x + acc2.x) * ivn, oy = (acc.y + acc2.y) * ivn;
        __nv_bfloat16 hx = __float2bfloat16(ox), hy = __float2bfloat16(oy);
        __nv_bfloat162 hh; hh.x = hx; hh.y = hy;
        __nv_bfloat162 ll;
        ll.x = __float2bfloat16(ox - __bfloat162float(hx));
        ll.y = __float2bfloat16(oy - __bfloat162float(hy));
        ((__nv_bfloat162*)Xhi)[(size_t)(node0 + nn) * 32 + lane] = hh;
        ((__nv_bfloat162*)Xlo)[(size_t)(node0 + nn) * 32 + lane] = ll;
    }
}

// ---------------- mma helper ----------------
#define MMA16816(c, a, b0, b1)                                             \
    asm volatile("mma.sync.aligned.m16n8k16.row.col.f32.bf16.bf16.f32 "    \
        "{%0,%1,%2,%3}, {%4,%5,%6,%7}, {%8,%9}, {%0,%1,%2,%3};"            \
        : "+f"((c)[0]), "+f"((c)[1]), "+f"((c)[2]), "+f"((c)[3])           \
        : "r"((a)[0]), "r"((a)[1]), "r"((a)[2]), "r"((a)[3]),              \
          "r"(b0), "r"(b1))

// ---- R12 full-width GEMM: CTA 128M x 128N, warp m32 x n64 ------------------------
// MODE 0: Y = inv[row]*acc      MODE 3: relu(acc+bias) -> bf16 hi/lo (Phi/Plo)
template <int K, int MODE>
__global__ void __launch_bounds__(256)
k_gemm_mma(const __nv_bfloat16* __restrict__ Xhi, const __nv_bfloat16* __restrict__ Xlo,
           const __nv_bfloat16* __restrict__ Whi, const __nv_bfloat16* __restrict__ Wlo,
           const float* __restrict__ bias, float* __restrict__ Y,
           __nv_bfloat16* __restrict__ Phi, __nv_bfloat16* __restrict__ Plo) {
    constexpr int KP = K + 8;
    extern __shared__ __nv_bfloat16 sB[];           // [2][128][KP]
    __nv_bfloat16* sBhi = sB;
    __nv_bfloat16* sBlo = sB + 128 * KP;

    int tid = threadIdx.x, wid = tid >> 5, lane = tid & 31;
    int q = lane & 3, g4 = lane >> 2;
    int m0 = blockIdx.x * 128 + (wid & 3) * 32;
    int nh = wid >> 2;

    for (int id = tid; id < 128 * (K / 8); id += 256) {
        int n = id / (K / 8), kb = (id % (K / 8)) * 8;
        *(float4*)&sBhi[n * KP + kb] = *(const float4*)(Whi + (size_t)n * K + kb);
        *(float4*)&sBlo[n * KP + kb] = *(const float4*)(Wlo + (size_t)n * K + kb);
    }
    __syncthreads();

    float c[2][8][4] = {};
    for (int kc = 0; kc < K / 16; kc++) {
        int k0 = kc * 16;
        uint32_t ah[2][4], al[2][4];
#pragma unroll
        for (int mh = 0; mh < 2; mh++) {
            size_t base = (size_t)(m0 + mh * 16 + g4) * K + k0 + q * 2;
            ah[mh][0] = *(const uint32_t*)(Xhi + base);
            ah[mh][1] = *(const uint32_t*)(Xhi + base + 8 * K);
            ah[mh][2] = *(const uint32_t*)(Xhi + base + 8);
            ah[mh][3] = *(const uint32_t*)(Xhi + base + 8 * K + 8);
            al[mh][0] = *(const uint32_t*)(Xlo + base);
            al[mh][1] = *(const uint32_t*)(Xlo + base + 8 * K);
            al[mh][2] = *(const uint32_t*)(Xlo + base + 8);
            al[mh][3] = *(const uint32_t*)(Xlo + base + 8 * K + 8);
        }
#pragma unroll
        for (int nc = 0; nc < 8; nc++) {
            int n = nh * 64 + nc * 8 + g4;
            const __nv_bfloat16* pb = &sBhi[n * KP + k0 + q * 2];
            const __nv_bfloat16* pl = &sBlo[n * KP + k0 + q * 2];
            uint32_t bh0 = *(const uint32_t*)pb, bh1 = *(const uint32_t*)(pb + 8);
            uint32_t bl0 = *(const uint32_t*)pl, bl1 = *(const uint32_t*)(pl + 8);
#pragma unroll
            for (int mh = 0; mh < 2; mh++) {
                MMA16816(c[mh][nc], ah[mh], bh0, bh1);
                MMA16816(c[mh][nc], ah[mh], bl0, bl1);
                MMA16816(c[mh][nc], al[mh], bh0, bh1);
            }
        }
    }

#pragma unroll
    for (int mh = 0; mh < 2; mh++) {
        int r0 = m0 + mh * 16 + g4;
        if (MODE == 0) {
            float s0 = g_inv[r0], s1 = g_inv[r0 + 8];
#pragma unroll
            for (int nc = 0; nc < 8; nc++) {
                int col = nh * 64 + nc * 8 + q * 2;
                *(float2*)(Y + (size_t)r0 * 128 + col) =
                    make_float2(c[mh][nc][0] * s0, c[mh][nc][1] * s0);
                *(float2*)(Y + (size_t)(r0 + 8) * 128 + col) =
                    make_float2(c[mh][nc][2] * s1, c[mh][nc][3] * s1);
            }
        } else {
#pragma unroll
            for (int nc = 0; nc < 8; nc++) {
                int col = nh * 64 + nc * 8 + q * 2;
                float b0 = __ldg(bias + col), b1 = __ldg(bias + col + 1);
                float t0 = fmaxf(c[mh][nc][0] + b0, 0.f);
                float t1 = fmaxf(c[mh][nc][1] + b1, 0.f);
                float t2 = fmaxf(c[mh][nc][2] + b0, 0.f);
                float t3 = fmaxf(c[mh][nc][3] + b1, 0.f);
                __nv_bfloat16 h0 = __float2bfloat16(t0), h1 = __float2bfloat16(t1);
                __nv_bfloat162 hh; hh.x = h0; hh.y = h1;
                __nv_bfloat162 ll;
                ll.x = __float2bfloat16(t0 - __bfloat162float(h0));
                ll.y = __float2bfloat16(t1 - __bfloat162float(h1));
                *(__nv_bfloat162*)(Phi + (size_t)r0 * 128 + col) = hh;
                *(__nv_bfloat162*)(Plo + (size_t)r0 * 128 + col) = ll;
                __nv_bfloat16 h2 = __float2bfloat16(t2), h3 = __float2bfloat16(t3);
                __nv_bfloat162 hh2; hh2.x = h2; hh2.y = h3;
                __nv_bfloat162 ll2;
                ll2.x = __float2bfloat16(t2 - __bfloat162float(h2));
                ll2.y = __float2bfloat16(t3 - __bfloat162float(h3));
                *(__nv_bfloat162*)(Phi + (size_t)(r0 + 8) * 128 + col) = hh2;
                *(__nv_bfloat162*)(Plo + (size_t)(r0 + 8) * 128 + col) = ll2;
            }
        }
    }
}

// ---- heads GEMM: grid = 3*gg. p=0 fused node head -> out; p=1/2 store A/Bm ------
__global__ void __launch_bounds__(256)
k_heads(const __nv_bfloat16* __restrict__ Xhi, const __nv_bfloat16* __restrict__ Xlo,
        const float* __restrict__ bn1, const float* __restrict__ wn2,
        const float* __restrict__ bn2, float* __restrict__ out, int MA,
        float* __restrict__ Ya, float* __restrict__ Yb, int gg) {
    constexpr int K = 128, KP = K + 8;
    extern __shared__ __nv_bfloat16 sB[];
    __nv_bfloat16* sBhi = sB;
    __nv_bfloat16* sBlo = sB + 128 * KP;
    __shared__ float slg[2][128][4];

    int p = blockIdx.x / gg;                       // 0: node head, 1: A, 2: Bm
    int mb = blockIdx.x - p * gg;
    const __nv_bfloat16* Whi = g_Whi + (3 + p) * 16384;
    const __nv_bfloat16* Wlo = g_Wlo + (3 + p) * 16384;

    int tid = threadIdx.x, wid = tid >> 5, lane = tid & 31;
    int q = lane & 3, g4 = lane >> 2;
    int m0 = mb * 128 + (wid & 3) * 32;
    int nh = wid >> 2;

    for (int id = tid; id < 128 * (K / 8); id += 256) {
        int n = id / (K / 8), kb = (id % (K / 8)) * 8;
        *(float4*)&sBhi[n * KP + kb] = *(const float4*)(Whi + (size_t)n * K + kb);
        *(float4*)&sBlo[n * KP + kb] = *(const float4*)(Wlo + (size_t)n * K + kb);
    }
    __syncthreads();

    float c[2][8][4] = {};
    for (int kc = 0; kc < K / 16; kc++) {
        int k0 = kc * 16;
        uint32_t ah[2][4], al[2][4];
#pragma unroll
        for (int mh = 0; mh < 2; mh++) {
            size_t base = (size_t)(m0 + mh * 16 + g4) * K + k0 + q * 2;
            ah[mh][0] = *(const uint32_t*)(Xhi + base);
            ah[mh][1] = *(const uint32_t*)(Xhi + base + 8 * K);
            ah[mh][2] = *(const uint32_t*)(Xhi + base + 8);
            ah[mh][3] = *(const uint32_t*)(Xhi + base + 8 * K + 8);
            al[mh][0] = *(const uint32_t*)(Xlo + base);
            al[mh][1] = *(const uint32_t*)(Xlo + base + 8 * K);
            al[mh][2] = *(const uint32_t*)(Xlo + base + 8);
            al[mh][3] = *(const uint32_t*)(Xlo + base + 8 * K + 8);
        }
#pragma unroll
        for (int nc = 0; nc < 8; nc++) {
            int n = nh * 64 + nc * 8 + g4;
            const __nv_bfloat16* pb = &sBhi[n * KP + k0 + q * 2];
            const __nv_bfloat16* pl = &sBlo[n * KP + k0 + q * 2];
            uint32_t bh0 = *(const uint32_t*)pb, bh1 = *(const uint32_t*)(pb + 8);
            uint32_t bl0 = *(const uint32_t*)pl, bl1 = *(const uint32_t*)(pl + 8);
#pragma unroll
            for (int mh = 0; mh < 2; mh++) {
                MMA16816(c[mh][nc], ah[mh], bh0, bh1);
                MMA16816(c[mh][nc], ah[mh], bl0, bl1);
                MMA16816(c[mh][nc], al[mh], bh0, bh1);
            }
        }
    }

    if (p != 0) {
        float* Y = (p == 1) ? Ya : Yb;
#pragma unroll
        for (int mh = 0; mh < 2; mh++) {
            int r0 = m0 + mh * 16 + g4;
#pragma unroll
            for (int nc = 0; nc < 8; nc++) {
                int col = nh * 64 + nc * 8 + q * 2;
                *(float2*)(Y + (size_t)r0 * 128 + col) =
                    make_float2(c[mh][nc][0], c[mh][nc][1]);
                *(float2*)(Y + (size_t)(r0 + 8) * 128 + col) =
                    make_float2(c[mh][nc][2], c[mh][nc][3]);
            }
        }
        return;
    }
    float lg[4][4] = {};
#pragma unroll
    for (int mh = 0; mh < 2; mh++) {
#pragma unroll
        for (int nc = 0; nc < 8; nc++) {
            int col = nh * 64 + nc * 8 + q * 2;
            float b0 = __ldg(bn1 + col), b1 = __ldg(bn1 + col + 1);
            float4 w0 = __ldg((const float4*)wn2 + col);
            float4 w1 = __ldg((const float4*)wn2 + col + 1);
            float t0 = fmaxf(c[mh][nc][0] + b0, 0.f);
            float t1 = fmaxf(c[mh][nc][1] + b1, 0.f);
            float t2 = fmaxf(c[mh][nc][2] + b0, 0.f);
            float t3 = fmaxf(c[mh][nc][3] + b1, 0.f);
            int ra = mh * 2, rb = mh * 2 + 1;
            lg[ra][0] += t0 * w0.x + t1 * w1.x;
            lg[ra][1] += t0 * w0.y + t1 * w1.y;
            lg[ra][2] += t0 * w0.z + t1 * w1.z;
            lg[ra][3] += t0 * w0.w + t1 * w1.w;
            lg[rb][0] += t2 * w0.x + t3 * w1.x;
            lg[rb][1] += t2 * w0.y + t3 * w1.y;
            lg[rb][2] += t2 * w0.z + t3 * w1.z;
            lg[rb][3] += t2 * w0.w + t3 * w1.w;
        }
    }
#pragma unroll
    for (int i = 0; i < 4; i++)
#pragma unroll
        for (int a = 0; a < 4; a++) {
            lg[i][a] += __shfl_xor_sync(0xffffffffu, lg[i][a], 1);
            lg[i][a] += __shfl_xor_sync(0xffffffffu, lg[i][a], 2);
        }
    if (q == 0) {
        int lr0 = (wid & 3) * 32 + g4;
#pragma unroll
        for (int i = 0; i < 4; i++) {
            int lr = lr0 + ((i & 1) ? 8 : 0) + ((i >> 1) ? 16 : 0);
#pragma unroll
            for (int a = 0; a < 4; a++) slg[nh][lr][a] = lg[i][a];
        }
    }
    __syncthreads();
    for (int id = tid; id < 512; id += 256) {
        int lr = id >> 2, a = id & 3;
        int R = mb * 128 + lr;
        int g = R >> 9, ln = R & 511;
        out[(size_t)g * MA + ln * 4 + a] =
            slg[0][lr][a] + slg[1][lr][a] + __ldg(bn2 + a);
    }
}

// ---- GCN aggregation (layers 2/3), smem-staged dim-quarters + optional pool ------
__global__ void __launch_bounds__(512)
k_gatherq(const float* __restrict__ U, const float* __restrict__ bias,
          __nv_bfloat16* __restrict__ Hhi, __nv_bfloat16* __restrict__ Hlo,
          int n_per, float* __restrict__ Gout) {
    extern __shared__ float sU[];                 // [512][33]
    __shared__ float spool[16][33];
    int b = blockIdx.x;
    int g = b >> 2, q = b & 3;
    int qd = q * 32;
    int tid = threadIdx.x, wid = tid >> 5, lane = tid & 31;
    int node0 = g * n_per;

    for (int i = tid; i < n_per * 32; i += 512) {
        int row = i >> 5, c = i & 31;
        sU[row * 33 + c] = U[(size_t)(node0 + row) * 128 + qd + c];
    }
    __syncthreads();

    float bb = __ldg(bias + qd + lane);
    float psum = 0.f;
    for (int nn = wid; nn < n_per; nn += 16) {
        float acc = sU[nn * 33 + lane];
        float acc2 = 0.f;
        int s = g_rs[node0 + nn], e = g_rs[node0 + nn + 1], j = s;
        for (; j + 1 < e; j += 2) {
            int a = g_csr[j] - node0, bn = g_csr[j + 1] - node0;
            acc  += sU[a * 33 + lane];
            acc2 += sU[bn * 33 + lane];
        }
        if (j < e) acc += sU[(g_csr[j] - node0) * 33 + lane];
        float iv = g_inv[node0 + nn];
        float o = fmaxf(fmaf(acc + acc2, iv, bb), 0.f);
        psum += o;
        __nv_bfloat16 h = __float2bfloat16(o);
        size_t idx = (size_t)(node0 + nn) * 128 + qd + lane;
        Hhi[idx] = h;
        Hlo[idx] = __float2bfloat16(o - __bfloat162float(h));
    }
    if (Gout != nullptr) {
        spool[wid][lane] = psum;
        __syncthreads();
        if (tid < 32) {
            float s = 0.f;
#pragma unroll
            for (int w = 0; w < 16; w++) s += spool[w][tid];
            Gout[g * 128 + qd + tid] = s / (float)n_per;
        }
    }
}

// ---- edge head + value head merged (R12) ----------------------------------------
#define EQ_STRIDE 36
__global__ void __launch_bounds__(512)
k_edgev(const float* __restrict__ A, const float* __restrict__ Bm,
        const int* __restrict__ ei, const float* __restrict__ be1,
        const float* __restrict__ we2, const float* __restrict__ be2,
        float* __restrict__ out, int E, int n_per, int e_per, int MA, int nblk,
        int B, const float* __restrict__ wv1, const float* __restrict__ bv1,
        const float* __restrict__ wv2, const float* __restrict__ bv2, int voff) {
    extern __shared__ float sm[];
    int b = blockIdx.x;
    int tid = threadIdx.x;
    if (b >= 2 * B) {
        int g = b - 2 * B;
        float* gs  = sm;
        float* red = sm + 128;
        if (tid < 128) gs[tid] = g_G[g * 128 + tid];
        __syncthreads();
        if (tid < 128) {
            float acc = bv1[tid];
#pragma unroll
            for (int k = 0; k < 128; k++) acc = fmaf(gs[k], wv1[k * 128 + tid], acc);
            red[tid] = fmaxf(acc, 0.f) * wv2[tid];
        }
        __syncthreads();
        for (int off = 64; off; off >>= 1) {
            if (tid < off) red[tid] += red[tid + off];
            __syncthreads();
        }
        if (tid == 0) out[voff + g] = red[0] + bv2[0];
        return;
    }
    float* sA = sm;
    float* sB = sm + n_per * EQ_STRIDE;
    __shared__ float swb[32][4];
    int g = b >> 1, eh = b & 1;
    int node0 = g * n_per;
    int ehalf = e_per >> 1;
    int e0 = g * e_per + eh * ehalf;

    int srcs[8], dsts[8];
#pragma unroll
    for (int j = 0; j < 8; j++) {
        int ge = e0 + tid + j * 512;
        srcs[j] = (ei[ge] - node0) * EQ_STRIDE;
        dsts[j] = (ei[E + ge] - node0) * EQ_STRIDE;
    }
    float p0[8], p1[8];
#pragma unroll
    for (int j = 0; j < 8; j++) { p0[j] = 0.f; p1[j] = 0.f; }

    for (int q = 0; q < 4; q++) {
        int qd = q * 32;
        __syncthreads();
        for (int i = tid; i < n_per * 8; i += 512) {
            int row = i >> 3, c = (i & 7) << 2;
            *(float4*)&sA[row * EQ_STRIDE + c] =
                *(const float4*)(A + (size_t)(node0 + row) * 128 + qd + c);
            *(float4*)&sB[row * EQ_STRIDE + c] =
                *(const float4*)(Bm + (size_t)(node0 + row) * 128 + qd + c);
        }
        if (tid < 32) {
            swb[tid][0] = we2[(qd + tid) * 2];
            swb[tid][1] = we2[(qd + tid) * 2 + 1];
            swb[tid][2] = be1[qd + tid];
        }
        __syncthreads();
#pragma unroll
        for (int j = 0; j < 8; j++) {
            int s = srcs[j], dd = dsts[j];
            float a0 = p0[j], a1 = p1[j];
#pragma unroll
            for (int d = 0; d < 32; d += 4) {
                float4 a4 = *(const float4*)&sA[s + d];
                float4 b4 = *(const float4*)&sB[dd + d];
                float t;
                t = fmaxf(a4.x + b4.x + swb[d][2], 0.f);
                a0 += t * swb[d][0]; a1 += t * swb[d][1];
                t = fmaxf(a4.y + b4.y + swb[d + 1][2], 0.f);
                a0 += t * swb[d + 1][0]; a1 += t * swb[d + 1][1];
                t = fmaxf(a4.z + b4.z + swb[d + 2][2], 0.f);
                a0 += t * swb[d + 2][0]; a1 += t * swb[d + 2][1];
                t = fmaxf(a4.w + b4.w + swb[d + 3][2], 0.f);
                a0 += t * swb[d + 3][0]; a1 += t * swb[d + 3][1];
            }
            p0[j] = a0; p1[j] = a1;
        }
    }
    float bb0 = __ldg(be2), bb1 = __ldg(be2 + 1);
    size_t obase = (size_t)g * MA + nblk;
    int le0 = eh * ehalf;
#pragma unroll
    for (int j = 0; j < 8; j++) {
        int le = le0 + tid + j * 512;
        *(float2*)&out[obase + (size_t)le * 2] = make_float2(p0[j] + bb0, p1[j] + bb1);
    }
}

// ---------------- launch ----------------
extern "C" void kernel_launch(void* const* d_in, const int* in_sizes, int n_in,
                              void* d_out, int out_size) {
    const float* x  = (const float*)d_in[0];
    const int*   ei = (const int*)d_in[1];
    int N = in_sizes[0] / 64;
    int E = in_sizes[1] / 2;

    int wb = n_in - 18;
    const float* w_g1 = (const float*)d_in[wb + 0];
    const float* b_g1 = (const float*)d_in[wb + 1];
    const float* w_g2 = (const float*)d_in[wb + 2];
    const float* b_g2 = (const float*)d_in[wb + 3];
    const float* w_g3 = (const float*)d_in[wb + 4];
    const float* b_g3 = (const float*)d_in[wb + 5];
    const float* wn1  = (const float*)d_in[wb + 6];
    const float* bn1  = (const float*)d_in[wb + 7];
    const float* wn2  = (const float*)d_in[wb + 8];
    const float* bn2  = (const float*)d_in[wb + 9];
    const float* we1  = (const float*)d_in[wb + 10];
    const float* be1  = (const float*)d_in[wb + 11];
    const float* we2  = (const float*)d_in[wb + 12];
    const float* be2  = (const float*)d_in[wb + 13];
    const float* wv1  = (const float*)d_in[wb + 14];
    const float* bv1  = (const float*)d_in[wb + 15];
    const float* wv2  = (const float*)d_in[wb + 16];
    const float* bv2  = (const float*)d_in[wb + 17];

    const int n_per = 512;
    int B     = N / n_per;
    int e_per = E / B;
    int MA    = n_per * 4 + e_per * 2;
    int voff  = out_size - B;
    float* out = (float*)d_out;

    float *U, *A, *Bm, *G;
    __nv_bfloat16 *Hhi, *Hlo, *Xhi, *Xlo, *Whi, *Wlo;
    cudaGetSymbolAddress((void**)&U,   g_U);
    cudaGetSymbolAddress((void**)&A,   g_A);
    cudaGetSymbolAddress((void**)&Bm,  g_B);
    cudaGetSymbolAddress((void**)&G,   g_G);
    cudaGetSymbolAddress((void**)&Hhi, g_Hhi);
    cudaGetSymbolAddress((void**)&Hlo, g_Hlo);
    cudaGetSymbolAddress((void**)&Xhi, g_Xhi);
    cudaGetSymbolAddress((void**)&Xlo, g_Xlo);
    cudaGetSymbolAddress((void**)&Whi, g_Whi);
    cudaGetSymbolAddress((void**)&Wlo, g_Wlo);

    const int SM64  = 2 * 128 * (64 + 8)  * 2;     // 36,864 B
    const int SM128 = 2 * 128 * (128 + 8) * 2;     // 69,632 B
    const int SMEQ  = n_per * EQ_STRIDE * 4 * 2;   // 147,456 B
    const int SMGQ  = n_per * 33 * 4;              // 67,584 B
    const int SMGF  = n_per * 66 * 4;              // 135,168 B (fused csr+gather)
    cudaFuncSetAttribute(k_csrg,             cudaFuncAttributeMaxDynamicSharedMemorySize, SMGF);
    cudaFuncSetAttribute(k_gemm_mma<64, 3>,  cudaFuncAttributeMaxDynamicSharedMemorySize, SM64);
    cudaFuncSetAttribute(k_gemm_mma<128, 0>, cudaFuncAttributeMaxDynamicSharedMemorySize, SM128);
    cudaFuncSetAttribute(k_heads,            cudaFuncAttributeMaxDynamicSharedMemorySize, SM128);
    cudaFuncSetAttribute(k_edgev,            cudaFuncAttributeMaxDynamicSharedMemorySize, SMEQ);
    cudaFuncSetAttribute(k_gatherq,          cudaFuncAttributeMaxDynamicSharedMemorySize, SMGQ);

    int gg = N / 128;

    // (1) fused CSR build + prescale(smem) + layer-1 gather + weight conversion
    k_csrg<<<B + 6, 512, SMGF>>>(ei, x, Xhi, Xlo, E, n_per, e_per, B,
                                 w_g1, w_g2, w_g3, wn1, we1, we1 + 128 * 128);
    // (2) layer-1 GEMM
    k_gemm_mma<64, 3><<<gg, 256, SM64>>>(Xhi, Xlo, Whi + 0 * 16384, Wlo + 0 * 16384,
                                         b_g1, nullptr, Hhi, Hlo);
    // layer 2
    k_gemm_mma<128, 0><<<gg, 256, SM128>>>(Hhi, Hlo, Whi + 1 * 16384, Wlo + 1 * 16384,
                                           nullptr, U, nullptr, nullptr);
    k_gatherq<<<B * 4, 512, SMGQ>>>(U, b_g2, Hhi, Hlo, n_per, nullptr);
    // layer 3 (+ fused mean pool)
    k_gemm_mma<128, 0><<<gg, 256, SM128>>>(Hhi, Hlo, Whi + 2 * 16384, Wlo + 2 * 16384,
                                           nullptr, U, nullptr, nullptr);
    k_gatherq<<<B * 4, 512, SMGQ>>>(U, b_g3, Hhi, Hlo, n_per, G);

    // heads: node (fused) + edge A + edge Bm in one launch
    k_heads<<<3 * gg, 256, SM128>>>(Hhi, Hlo, bn1, wn2, bn2, out, MA, A, Bm, gg);

    // edge head + value head in one launch
    k_edgev<<<B * 2 + B, 512, SMEQ>>>(A, Bm, ei, be1, we2, be2, out,
                                      E, n_per, e_per, MA, n_per * 4,
                                      B, wv1, bv1, wv2, bv2, voff);
}

// round 16
// speedup vs baseline: 1.0735x; 1.0280x over previous
#include <cuda_runtime.h>
#include <cuda_bf16.h>
#include <cstdint>

#define NMAX 32768
#define EMAX 524288

// ---------------- scratch (static device globals; no allocation) ----------------
__device__ float g_U [NMAX * 128];
__device__ float g_A [NMAX * 128];
__device__ float g_B [NMAX * 128];
__device__ __nv_bfloat16 g_Hhi[NMAX * 128];
__device__ __nv_bfloat16 g_Hlo[NMAX * 128];
__device__ __nv_bfloat16 g_Xhi[NMAX * 64];
__device__ __nv_bfloat16 g_Xlo[NMAX * 64];
__device__ __nv_bfloat16 g_Whi[6 * 128 * 128];
__device__ __nv_bfloat16 g_Wlo[6 * 128 * 128];
__device__ float g_inv[NMAX];
__device__ int   g_rs [NMAX + 1];
__device__ int   g_csr[EMAX];
__device__ float g_G  [64 * 128];

// ---- fused: CSR build + prescale(into smem) + layer-1 gather + weight conv ------
__global__ void __launch_bounds__(512)
k_csrg(const int* __restrict__ ei, const float* __restrict__ x,
       __nv_bfloat16* __restrict__ Xhi, __nv_bfloat16* __restrict__ Xlo,
       int E, int n_per, int e_per, int B,
       const float* w0, const float* w1, const float* w2,
       const float* w3, const float* w4, const float* w5) {
    int blk = blockIdx.x, tid = threadIdx.x;
    if (blk >= B) {
        int b = blk - B;
        const float* srcs[6] = {w0, w1, w2, w3, w4, w5};
        const int Ks[6] = {64, 128, 128, 128, 128, 128};
        const float* W = srcs[b];
        int K = Ks[b];
        __nv_bfloat16* oh = g_Whi + b * 16384;
        __nv_bfloat16* ol = g_Wlo + b * 16384;
        for (int id = tid; id < 128 * K; id += 512) {
            int n = id / K, k = id % K;
            float v = W[k * 128 + n];             // transpose: Wt[n,k] = W[k,n]
            __nv_bfloat16 h = __float2bfloat16(v);
            oh[id] = h;
            ol[id] = __float2bfloat16(v - __bfloat162float(h));
        }
        return;
    }
    extern __shared__ float sU[];                 // [512][66] staged xs
    __shared__ int cnt[512];
    __shared__ int off[512];
    __shared__ float sinv[512];
    int g = blk;
    int node0 = g * n_per;
    int ebase = g * e_per;
    int wid = tid >> 5, lane = tid & 31;

    cnt[tid] = 0;
    __syncthreads();
    for (int j = tid; j < e_per; j += 512)
        atomicAdd(&cnt[ei[E + ebase + j] - node0], 1);
    __syncthreads();
    int v = cnt[tid];
    off[tid] = v;
    __syncthreads();
#pragma unroll
    for (int s = 1; s < 512; s <<= 1) {
        int t = (tid >= s) ? off[tid - s] : 0;
        __syncthreads();
        off[tid] += t;
        __syncthreads();
    }
    int excl = off[tid] - v;
    float iv = rsqrtf((float)(v + 1));
    g_rs[node0 + tid] = ebase + excl;
    g_inv[node0 + tid] = iv;
    sinv[tid] = iv;
    if (tid == 511) g_rs[node0 + 512] = ebase + e_per;
    cnt[tid] = ebase + excl;                      // reuse as global cursor
    __syncthreads();
    for (int j = tid; j < e_per; j += 512) {
        int src = ei[ebase + j];
        int ld  = ei[E + ebase + j] - node0;
        int pos = atomicAdd(&cnt[ld], 1);
        g_csr[pos] = src;
    }
    // prescale into smem
    const float2* xg = (const float2*)x;
    size_t base2 = (size_t)node0 * 32;
    for (int i = tid; i < n_per * 32; i += 512) {
        int row = i >> 5, l = i & 31;
        float2 vv = xg[base2 + i];
        float s = sinv[row];
        vv.x *= s; vv.y *= s;
        ((float2*)sU)[row * 33 + l] = vv;
    }
    __syncthreads();

    // layer-1 gather: warp per node, lane = 2 dims
    const float2* sU2 = (const float2*)sU;
    for (int nn = wid; nn < n_per; nn += 16) {
        float2 acc = sU2[nn * 33 + lane];         // self loop
        float2 acc2 = make_float2(0.f, 0.f);
        int s = g_rs[node0 + nn], e = g_rs[node0 + nn + 1], j = s;
        for (; j + 1 < e; j += 2) {
            int a = g_csr[j] - node0, b2 = g_csr[j + 1] - node0;
            float2 v0 = sU2[a * 33 + lane], v1 = sU2[b2 * 33 + lane];
            acc.x += v0.x; acc.y += v0.y;
            acc2.x += v1.x; acc2.y += v1.y;
        }
        if (j < e) {
            float2 v0 = sU2[(g_csr[j] - node0) * 33 + lane];
            acc.x += v0.x; acc.y += v0.y;
        }
        float ivn = sinv[nn];
        float ox = (acc.x + acc2.x) * ivn, oy = (acc.y + acc2.y) * ivn;
        __nv_bfloat16 hx = __float2bfloat16(ox), hy = __float2bfloat16(oy);
        __nv_bfloat162 hh; hh.x = hx; hh.y = hy;
        __nv_bfloat162 ll;
        ll.x = __float2bfloat16(ox - __bfloat162float(hx));
        ll.y = __float2bfloat16(oy - __bfloat162float(hy));
        ((__nv_bfloat162*)Xhi)[(size_t)(node0 + nn) * 32 + lane] = hh;
        ((__nv_bfloat162*)Xlo)[(size_t)(node0 + nn) * 32 + lane] = ll;
    }
}

// ---------------- mma helper ----------------
#define MMA16816(c, a, b0, b1)                                             \
    asm volatile("mma.sync.aligned.m16n8k16.row.col.f32.bf16.bf16.f32 "    \
        "{%0,%1,%2,%3}, {%4,%5,%6,%7}, {%8,%9}, {%0,%1,%2,%3};"            \
        : "+f"((c)[0]), "+f"((c)[1]), "+f"((c)[2]), "+f"((c)[3])           \
        : "r"((a)[0]), "r"((a)[1]), "r"((a)[2]), "r"((a)[3]),              \
          "r"(b0), "r"(b1))

// ---- full-width GEMM (R12): CTA 128M x 128N, warp m32 x n64 ---------------------
template <int K, int MODE>
__global__ void __launch_bounds__(256)
k_gemm_mma(const __nv_bfloat16* __restrict__ Xhi, const __nv_bfloat16* __restrict__ Xlo,
           const __nv_bfloat16* __restrict__ Whi, const __nv_bfloat16* __restrict__ Wlo,
           const float* __restrict__ bias, float* __restrict__ Y,
           __nv_bfloat16* __restrict__ Phi, __nv_bfloat16* __restrict__ Plo) {
    constexpr int KP = K + 8;
    extern __shared__ __nv_bfloat16 sB[];
    __nv_bfloat16* sBhi = sB;
    __nv_bfloat16* sBlo = sB + 128 * KP;

    int tid = threadIdx.x, wid = tid >> 5, lane = tid & 31;
    int q = lane & 3, g4 = lane >> 2;
    int m0 = blockIdx.x * 128 + (wid & 3) * 32;
    int nh = wid >> 2;

    for (int id = tid; id < 128 * (K / 8); id += 256) {
        int n = id / (K / 8), kb = (id % (K / 8)) * 8;
        *(float4*)&sBhi[n * KP + kb] = *(const float4*)(Whi + (size_t)n * K + kb);
        *(float4*)&sBlo[n * KP + kb] = *(const float4*)(Wlo + (size_t)n * K + kb);
    }
    __syncthreads();

    float c[2][8][4] = {};
    for (int kc = 0; kc < K / 16; kc++) {
        int k0 = kc * 16;
        uint32_t ah[2][4], al[2][4];
#pragma unroll
        for (int mh = 0; mh < 2; mh++) {
            size_t base = (size_t)(m0 + mh * 16 + g4) * K + k0 + q * 2;
            ah[mh][0] = *(const uint32_t*)(Xhi + base);
            ah[mh][1] = *(const uint32_t*)(Xhi + base + 8 * K);
            ah[mh][2] = *(const uint32_t*)(Xhi + base + 8);
            ah[mh][3] = *(const uint32_t*)(Xhi + base + 8 * K + 8);
            al[mh][0] = *(const uint32_t*)(Xlo + base);
            al[mh][1] = *(const uint32_t*)(Xlo + base + 8 * K);
            al[mh][2] = *(const uint32_t*)(Xlo + base + 8);
            al[mh][3] = *(const uint32_t*)(Xlo + base + 8 * K + 8);
        }
#pragma unroll
        for (int nc = 0; nc < 8; nc++) {
            int n = nh * 64 + nc * 8 + g4;
            const __nv_bfloat16* pb = &sBhi[n * KP + k0 + q * 2];
            const __nv_bfloat16* pl = &sBlo[n * KP + k0 + q * 2];
            uint32_t bh0 = *(const uint32_t*)pb, bh1 = *(const uint32_t*)(pb + 8);
            uint32_t bl0 = *(const uint32_t*)pl, bl1 = *(const uint32_t*)(pl + 8);
#pragma unroll
            for (int mh = 0; mh < 2; mh++) {
                MMA16816(c[mh][nc], ah[mh], bh0, bh1);
                MMA16816(c[mh][nc], ah[mh], bl0, bl1);
                MMA16816(c[mh][nc], al[mh], bh0, bh1);
            }
        }
    }

#pragma unroll
    for (int mh = 0; mh < 2; mh++) {
        int r0 = m0 + mh * 16 + g4;
        if (MODE == 0) {
            float s0 = g_inv[r0], s1 = g_inv[r0 + 8];
#pragma unroll
            for (int nc = 0; nc < 8; nc++) {
                int col = nh * 64 + nc * 8 + q * 2;
                *(float2*)(Y + (size_t)r0 * 128 + col) =
                    make_float2(c[mh][nc][0] * s0, c[mh][nc][1] * s0);
                *(float2*)(Y + (size_t)(r0 + 8) * 128 + col) =
                    make_float2(c[mh][nc][2] * s1, c[mh][nc][3] * s1);
            }
        } else {
#pragma unroll
            for (int nc = 0; nc < 8; nc++) {
                int col = nh * 64 + nc * 8 + q * 2;
                float b0 = __ldg(bias + col), b1 = __ldg(bias + col + 1);
                float t0 = fmaxf(c[mh][nc][0] + b0, 0.f);
                float t1 = fmaxf(c[mh][nc][1] + b1, 0.f);
                float t2 = fmaxf(c[mh][nc][2] + b0, 0.f);
                float t3 = fmaxf(c[mh][nc][3] + b1, 0.f);
                __nv_bfloat16 h0 = __float2bfloat16(t0), h1 = __float2bfloat16(t1);
                __nv_bfloat162 hh; hh.x = h0; hh.y = h1;
                __nv_bfloat162 ll;
                ll.x = __float2bfloat16(t0 - __bfloat162float(h0));
                ll.y = __float2bfloat16(t1 - __bfloat162float(h1));
                *(__nv_bfloat162*)(Phi + (size_t)r0 * 128 + col) = hh;
                *(__nv_bfloat162*)(Plo + (size_t)r0 * 128 + col) = ll;
                __nv_bfloat16 h2 = __float2bfloat16(t2), h3 = __float2bfloat16(t3);
                __nv_bfloat162 hh2; hh2.x = h2; hh2.y = h3;
                __nv_bfloat162 ll2;
                ll2.x = __float2bfloat16(t2 - __bfloat162float(h2));
                ll2.y = __float2bfloat16(t3 - __bfloat162float(h3));
                *(__nv_bfloat162*)(Phi + (size_t)(r0 + 8) * 128 + col) = hh2;
                *(__nv_bfloat162*)(Plo + (size_t)(r0 + 8) * 128 + col) = ll2;
            }
        }
    }
}

// ---- heads GEMM: grid = 3*gg. p=0 fused node head -> out; p=1/2 store A/Bm ------
__global__ void __launch_bounds__(256)
k_heads(const __nv_bfloat16* __restrict__ Xhi, const __nv_bfloat16* __restrict__ Xlo,
        const float* __restrict__ bn1, const float* __restrict__ wn2,
        const float* __restrict__ bn2, float* __restrict__ out, int MA,
        float* __restrict__ Ya, float* __restrict__ Yb, int gg) {
    constexpr int K = 128, KP = K + 8;
    extern __shared__ __nv_bfloat16 sB[];
    __nv_bfloat16* sBhi = sB;
    __nv_bfloat16* sBlo = sB + 128 * KP;
    __shared__ float slg[2][128][4];

    int p = blockIdx.x / gg;
    int mb = blockIdx.x - p * gg;
    const __nv_bfloat16* Whi = g_Whi + (3 + p) * 16384;
    const __nv_bfloat16* Wlo = g_Wlo + (3 + p) * 16384;

    int tid = threadIdx.x, wid = tid >> 5, lane = tid & 31;
    int q = lane & 3, g4 = lane >> 2;
    int m0 = mb * 128 + (wid & 3) * 32;
    int nh = wid >> 2;

    for (int id = tid; id < 128 * (K / 8); id += 256) {
        int n = id / (K / 8), kb = (id % (K / 8)) * 8;
        *(float4*)&sBhi[n * KP + kb] = *(const float4*)(Whi + (size_t)n * K + kb);
        *(float4*)&sBlo[n * KP + kb] = *(const float4*)(Wlo + (size_t)n * K + kb);
    }
    __syncthreads();

    float c[2][8][4] = {};
    for (int kc = 0; kc < K / 16; kc++) {
        int k0 = kc * 16;
        uint32_t ah[2][4], al[2][4];
#pragma unroll
        for (int mh = 0; mh < 2; mh++) {
            size_t base = (size_t)(m0 + mh * 16 + g4) * K + k0 + q * 2;
            ah[mh][0] = *(const uint32_t*)(Xhi + base);
            ah[mh][1] = *(const uint32_t*)(Xhi + base + 8 * K);
            ah[mh][2] = *(const uint32_t*)(Xhi + base + 8);
            ah[mh][3] = *(const uint32_t*)(Xhi + base + 8 * K + 8);
            al[mh][0] = *(const uint32_t*)(Xlo + base);
            al[mh][1] = *(const uint32_t*)(Xlo + base + 8 * K);
            al[mh][2] = *(const uint32_t*)(Xlo + base + 8);
            al[mh][3] = *(const uint32_t*)(Xlo + base + 8 * K + 8);
        }
#pragma unroll
        for (int nc = 0; nc < 8; nc++) {
            int n = nh * 64 + nc * 8 + g4;
            const __nv_bfloat16* pb = &sBhi[n * KP + k0 + q * 2];
            const __nv_bfloat16* pl = &sBlo[n * KP + k0 + q * 2];
            uint32_t bh0 = *(const uint32_t*)pb, bh1 = *(const uint32_t*)(pb + 8);
            uint32_t bl0 = *(const uint32_t*)pl, bl1 = *(const uint32_t*)(pl + 8);
#pragma unroll
            for (int mh = 0; mh < 2; mh++) {
                MMA16816(c[mh][nc], ah[mh], bh0, bh1);
                MMA16816(c[mh][nc], ah[mh], bl0, bl1);
                MMA16816(c[mh][nc], al[mh], bh0, bh1);
            }
        }
    }

    if (p != 0) {
        float* Y = (p == 1) ? Ya : Yb;
#pragma unroll
        for (int mh = 0; mh < 2; mh++) {
            int r0 = m0 + mh * 16 + g4;
#pragma unroll
            for (int nc = 0; nc < 8; nc++) {
                int col = nh * 64 + nc * 8 + q * 2;
                *(float2*)(Y + (size_t)r0 * 128 + col) =
                    make_float2(c[mh][nc][0], c[mh][nc][1]);
                *(float2*)(Y + (size_t)(r0 + 8) * 128 + col) =
                    make_float2(c[mh][nc][2], c[mh][nc][3]);
            }
        }
        return;
    }
    float lg[4][4] = {};
#pragma unroll
    for (int mh = 0; mh < 2; mh++) {
#pragma unroll
        for (int nc = 0; nc < 8; nc++) {
            int col = nh * 64 + nc * 8 + q * 2;
            float b0 = __ldg(bn1 + col), b1 = __ldg(bn1 + col + 1);
            float4 w0 = __ldg((const float4*)wn2 + col);
            float4 w1 = __ldg((const float4*)wn2 + col + 1);
            float t0 = fmaxf(c[mh][nc][0] + b0, 0.f);
            float t1 = fmaxf(c[mh][nc][1] + b1, 0.f);
            float t2 = fmaxf(c[mh][nc][2] + b0, 0.f);
            float t3 = fmaxf(c[mh][nc][3] + b1, 0.f);
            int ra = mh * 2, rb = mh * 2 + 1;
            lg[ra][0] += t0 * w0.x + t1 * w1.x;
            lg[ra][1] += t0 * w0.y + t1 * w1.y;
            lg[ra][2] += t0 * w0.z + t1 * w1.z;
            lg[ra][3] += t0 * w0.w + t1 * w1.w;
            lg[rb][0] += t2 * w0.x + t3 * w1.x;
            lg[rb][1] += t2 * w0.y + t3 * w1.y;
            lg[rb][2] += t2 * w0.z + t3 * w1.z;
            lg[rb][3] += t2 * w0.w + t3 * w1.w;
        }
    }
#pragma unroll
    for (int i = 0; i < 4; i++)
#pragma unroll
        for (int a = 0; a < 4; a++) {
            lg[i][a] += __shfl_xor_sync(0xffffffffu, lg[i][a], 1);
            lg[i][a] += __shfl_xor_sync(0xffffffffu, lg[i][a], 2);
        }
    if (q == 0) {
        int lr0 = (wid & 3) * 32 + g4;
#pragma unroll
        for (int i = 0; i < 4; i++) {
            int lr = lr0 + ((i & 1) ? 8 : 0) + ((i >> 1) ? 16 : 0);
#pragma unroll
            for (int a = 0; a < 4; a++) slg[nh][lr][a] = lg[i][a];
        }
    }
    __syncthreads();
    for (int id = tid; id < 512; id += 256) {
        int lr = id >> 2, a = id & 3;
        int R = mb * 128 + lr;
        int g = R >> 9, ln = R & 511;
        out[(size_t)g * MA + ln * 4 + a] =
            slg[0][lr][a] + slg[1][lr][a] + __ldg(bn2 + a);
    }
}

// ---- GCN aggregation (layers 2/3): block=(g, half of 128 dims), lane = 2 dims ----
// float2 LDS + 4-deep unrolled neighbor loop (4 independent accumulator chains).
__global__ void __launch_bounds__(512)
k_gatherh(const float* __restrict__ U, const float* __restrict__ bias,
          __nv_bfloat16* __restrict__ Hhi, __nv_bfloat16* __restrict__ Hlo,
          int n_per, float* __restrict__ Gout) {
    extern __shared__ float sU[];                 // float2 [512][33]
    __shared__ float spool[16][66];
    int b = blockIdx.x;
    int g = b >> 1, hh = b & 1;
    int qd = hh * 64;
    int tid = threadIdx.x, wid = tid >> 5, lane = tid & 31;
    int node0 = g * n_per;

    for (int i = tid; i < n_per * 32; i += 512) {
        int row = i >> 5, l = i & 31;
        ((float2*)sU)[row * 33 + l] =
            *(const float2*)(U + (size_t)(node0 + row) * 128 + qd + 2 * l);
    }
    __syncthreads();

    const float2* sU2 = (const float2*)sU;
    float2 bb = *(const float2*)(bias + qd + 2 * lane);
    float px = 0.f, py = 0.f;
    for (int nn = wid; nn < n_per; nn += 16) {
        float2 a0 = sU2[nn * 33 + lane];          // self loop
        float2 a1 = make_float2(0.f, 0.f);
        float2 a2 = make_float2(0.f, 0.f);
        float2 a3 = make_float2(0.f, 0.f);
        int s = g_rs[node0 + nn], e = g_rs[node0 + nn + 1], j = s;
        for (; j + 3 < e; j += 4) {
            int i0 = g_csr[j]     - node0;
            int i1 = g_csr[j + 1] - node0;
            int i2 = g_csr[j + 2] - node0;
            int i3 = g_csr[j + 3] - node0;
            float2 v0 = sU2[i0 * 33 + lane];
            float2 v1 = sU2[i1 * 33 + lane];
            float2 v2 = sU2[i2 * 33 + lane];
            float2 v3 = sU2[i3 * 33 + lane];
            a0.x += v0.x; a0.y += v0.y;
            a1.x += v1.x; a1.y += v1.y;
            a2.x += v2.x; a2.y += v2.y;
            a3.x += v3.x; a3.y += v3.y;
        }
        for (; j < e; j++) {
            float2 v0 = sU2[(g_csr[j] - node0) * 33 + lane];
            a0.x += v0.x; a0.y += v0.y;
        }
        float iv = g_inv[node0 + nn];
        float sx = (a0.x + a1.x) + (a2.x + a3.x);
        float sy = (a0.y + a1.y) + (a2.y + a3.y);
        float ox = fmaxf(fmaf(sx, iv, bb.x), 0.f);
        float oy = fmaxf(fmaf(sy, iv, bb.y), 0.f);
        px += ox; py += oy;
        __nv_bfloat16 hx = __float2bfloat16(ox), hy = __float2bfloat16(oy);
        __nv_bfloat162 hv; hv.x = hx; hv.y = hy;
        __nv_bfloat162 lv;
        lv.x = __float2bfloat16(ox - __bfloat162float(hx));
        lv.y = __float2bfloat16(oy - __bfloat162float(hy));
        ((__nv_bfloat162*)Hhi)[(size_t)(node0 + nn) * 64 + qd / 2 + lane] = hv;
        ((__nv_bfloat162*)Hlo)[(size_t)(node0 + nn) * 64 + qd / 2 + lane] = lv;
    }
    if (Gout != nullptr) {
        spool[wid][2 * lane]     = px;
        spool[wid][2 * lane + 1] = py;
        __syncthreads();
        if (tid < 64) {
            float s = 0.f;
#pragma unroll
            for (int w = 0; w < 16; w++) s += spool[w][tid];
            Gout[g * 128 + qd + tid] = s / (float)n_per;
        }
    }
}

// ---- edge head + value head merged (R12) ----------------------------------------
#define EQ_STRIDE 36
__global__ void __launch_bounds__(512)
k_edgev(const float* __restrict__ A, const float* __restrict__ Bm,
        const int* __restrict__ ei, const float* __restrict__ be1,
        const float* __restrict__ we2, const float* __restrict__ be2,
        float* __restrict__ out, int E, int n_per, int e_per, int MA, int nblk,
        int B, const float* __restrict__ wv1, const float* __restrict__ bv1,
        const float* __restrict__ wv2, const float* __restrict__ bv2, int voff) {
    extern __shared__ float sm[];
    int b = blockIdx.x;
    int tid = threadIdx.x;
    if (b >= 2 * B) {
        int g = b - 2 * B;
        float* gs  = sm;
        float* red = sm + 128;
        if (tid < 128) gs[tid] = g_G[g * 128 + tid];
        __syncthreads();
        if (tid < 128) {
            float acc = bv1[tid];
#pragma unroll
            for (int k = 0; k < 128; k++) acc = fmaf(gs[k], wv1[k * 128 + tid], acc);
            red[tid] = fmaxf(acc, 0.f) * wv2[tid];
        }
        __syncthreads();
        for (int off = 64; off; off >>= 1) {
            if (tid < off) red[tid] += red[tid + off];
            __syncthreads();
        }
        if (tid == 0) out[voff + g] = red[0] + bv2[0];
        return;
    }
    float* sA = sm;
    float* sB = sm + n_per * EQ_STRIDE;
    __shared__ float swb[32][4];
    int g = b >> 1, eh = b & 1;
    int node0 = g * n_per;
    int ehalf = e_per >> 1;
    int e0 = g * e_per + eh * ehalf;

    int srcs[8], dsts[8];
#pragma unroll
    for (int j = 0; j < 8; j++) {
        int ge = e0 + tid + j * 512;
        srcs[j] = (ei[ge] - node0) * EQ_STRIDE;
        dsts[j] = (ei[E + ge] - node0) * EQ_STRIDE;
    }
    float p0[8], p1[8];
#pragma unroll
    for (int j = 0; j < 8; j++) { p0[j] = 0.f; p1[j] = 0.f; }

    for (int q = 0; q < 4; q++) {
        int qd = q * 32;
        __syncthreads();
        for (int i = tid; i < n_per * 8; i += 512) {
            int row = i >> 3, c = (i & 7) << 2;
            *(float4*)&sA[row * EQ_STRIDE + c] =
                *(const float4*)(A + (size_t)(node0 + row) * 128 + qd + c);
            *(float4*)&sB[row * EQ_STRIDE + c] =
                *(const float4*)(Bm + (size_t)(node0 + row) * 128 + qd + c);
        }
        if (tid < 32) {
            swb[tid][0] = we2[(qd + tid) * 2];
            swb[tid][1] = we2[(qd + tid) * 2 + 1];
            swb[tid][2] = be1[qd + tid];
        }
        __syncthreads();
#pragma unroll
        for (int j = 0; j < 8; j++) {
            int s = srcs[j], dd = dsts[j];
            float a0 = p0[j], a1 = p1[j];
#pragma unroll
            for (int d = 0; d < 32; d += 4) {
                float4 a4 = *(const float4*)&sA[s + d];
                float4 b4 = *(const float4*)&sB[dd + d];
                float t;
                t = fmaxf(a4.x + b4.x + swb[d][2], 0.f);
                a0 += t * swb[d][0]; a1 += t * swb[d][1];
                t = fmaxf(a4.y + b4.y + swb[d + 1][2], 0.f);
                a0 += t * swb[d + 1][0]; a1 += t * swb[d + 1][1];
                t = fmaxf(a4.z + b4.z + swb[d + 2][2], 0.f);
                a0 += t * swb[d + 2][0]; a1 += t * swb[d + 2][1];
                t = fmaxf(a4.w + b4.w + swb[d + 3][2], 0.f);
                a0 += t * swb[d + 3][0]; a1 += t * swb[d + 3][1];
            }
            p0[j] = a0; p1[j] = a1;
        }
    }
    float bb0 = __ldg(be2), bb1 = __ldg(be2 + 1);
    size_t obase = (size_t)g * MA + nblk;
    int le0 = eh * ehalf;
#pragma unroll
    for (int j = 0; j < 8; j++) {
        int le = le0 + tid + j * 512;
        *(float2*)&out[obase + (size_t)le * 2] = make_float2(p0[j] + bb0, p1[j] + bb1);
    }
}

// ---------------- launch ----------------
extern "C" void kernel_launch(void* const* d_in, const int* in_sizes, int n_in,
                              void* d_out, int out_size) {
    const float* x  = (const float*)d_in[0];
    const int*   ei = (const int*)d_in[1];
    int N = in_sizes[0] / 64;
    int E = in_sizes[1] / 2;

    int wb = n_in - 18;
    const float* w_g1 = (const float*)d_in[wb + 0];
    const float* b_g1 = (const float*)d_in[wb + 1];
    const float* w_g2 = (const float*)d_in[wb + 2];
    const float* b_g2 = (const float*)d_in[wb + 3];
    const float* w_g3 = (const float*)d_in[wb + 4];
    const float* b_g3 = (const float*)d_in[wb + 5];
    const float* wn1  = (const float*)d_in[wb + 6];
    const float* bn1  = (const float*)d_in[wb + 7];
    const float* wn2  = (const float*)d_in[wb + 8];
    const float* bn2  = (const float*)d_in[wb + 9];
    const float* we1  = (const float*)d_in[wb + 10];
    const float* be1  = (const float*)d_in[wb + 11];
    const float* we2  = (const float*)d_in[wb + 12];
    const float* be2  = (const float*)d_in[wb + 13];
    const float* wv1  = (const float*)d_in[wb + 14];
    const float* bv1  = (const float*)d_in[wb + 15];
    const float* wv2  = (const float*)d_in[wb + 16];
    const float* bv2  = (const float*)d_in[wb + 17];

    const int n_per = 512;
    int B     = N / n_per;
    int e_per = E / B;
    int MA    = n_per * 4 + e_per * 2;
    int voff  = out_size - B;
    float* out = (float*)d_out;

    float *U, *A, *Bm, *G;
    __nv_bfloat16 *Hhi, *Hlo, *Xhi, *Xlo, *Whi, *Wlo;
    cudaGetSymbolAddress((void**)&U,   g_U);
    cudaGetSymbolAddress((void**)&A,   g_A);
    cudaGetSymbolAddress((void**)&Bm,  g_B);
    cudaGetSymbolAddress((void**)&G,   g_G);
    cudaGetSymbolAddress((void**)&Hhi, g_Hhi);
    cudaGetSymbolAddress((void**)&Hlo, g_Hlo);
    cudaGetSymbolAddress((void**)&Xhi, g_Xhi);
    cudaGetSymbolAddress((void**)&Xlo, g_Xlo);
    cudaGetSymbolAddress((void**)&Whi, g_Whi);
    cudaGetSymbolAddress((void**)&Wlo, g_Wlo);

    const int SM64  = 2 * 128 * (64 + 8)  * 2;     // 36,864 B
    const int SM128 = 2 * 128 * (128 + 8) * 2;     // 69,632 B
    const int SMEQ  = n_per * EQ_STRIDE * 4 * 2;   // 147,456 B
    const int SMGF  = n_per * 66 * 4;              // 135,168 B
    cudaFuncSetAttribute(k_csrg,             cudaFuncAttributeMaxDynamicSharedMemorySize, SMGF);
    cudaFuncSetAttribute(k_gemm_mma<64, 3>,  cudaFuncAttributeMaxDynamicSharedMemorySize, SM64);
    cudaFuncSetAttribute(k_gemm_mma<128, 0>, cudaFuncAttributeMaxDynamicSharedMemorySize, SM128);
    cudaFuncSetAttribute(k_heads,            cudaFuncAttributeMaxDynamicSharedMemorySize, SM128);
    cudaFuncSetAttribute(k_edgev,            cudaFuncAttributeMaxDynamicSharedMemorySize, SMEQ);
    cudaFuncSetAttribute(k_gatherh,          cudaFuncAttributeMaxDynamicSharedMemorySize, SMGF);

    int gg = N / 128;

    // (1) fused CSR build + prescale(smem) + layer-1 gather + weight conversion
    k_csrg<<<B + 6, 512, SMGF>>>(ei, x, Xhi, Xlo, E, n_per, e_per, B,
                                 w_g1, w_g2, w_g3, wn1, we1, we1 + 128 * 128);
    // (2) layer-1 GEMM
    k_gemm_mma<64, 3><<<gg, 256, SM64>>>(Xhi, Xlo, Whi + 0 * 16384, Wlo + 0 * 16384,
                                         b_g1, nullptr, Hhi, Hlo);
    // layer 2
    k_gemm_mma<128, 0><<<gg, 256, SM128>>>(Hhi, Hlo, Whi + 1 * 16384, Wlo + 1 * 16384,
                                           nullptr, U, nullptr, nullptr);
    k_gatherh<<<B * 2, 512, SMGF>>>(U, b_g2, Hhi, Hlo, n_per, nullptr);
    // layer 3 (+ fused mean pool)
    k_gemm_mma<128, 0><<<gg, 256, SM128>>>(Hhi, Hlo, Whi + 2 * 16384, Wlo + 2 * 16384,
                                           nullptr, U, nullptr, nullptr);
    k_gatherh<<<B * 2, 512, SMGF>>>(U, b_g3, Hhi, Hlo, n_per, G);

    // heads: node (fused) + edge A + edge Bm in one launch
    k_heads<<<3 * gg, 256, SM128>>>(Hhi, Hlo, bn1, wn2, bn2, out, MA, A, Bm, gg);

    // edge head + value head in one launch
    k_edgev<<<B * 2 + B, 512, SMEQ>>>(A, Bm, ei, be1, we2, be2, out,
                                      E, n_per, e_per, MA, n_per * 4,
                                      B, wv1, bv1, wv2, bv2, voff);
}

// round 17
// speedup vs baseline: 1.1495x; 1.0707x over previous
#include <cuda_runtime.h>
#include <cuda_bf16.h>
#include <cstdint>

#define NMAX 32768
#define EMAX 524288

// ---------------- scratch (static device globals; no allocation) ----------------
__device__ float g_U [NMAX * 128];
__device__ float g_A [NMAX * 128];
__device__ float g_B [NMAX * 128];
__device__ __nv_bfloat16 g_Hhi[NMAX * 128];
__device__ __nv_bfloat16 g_Hlo[NMAX * 128];
__device__ __nv_bfloat16 g_Xhi[NMAX * 64];
__device__ __nv_bfloat16 g_Xlo[NMAX * 64];
__device__ __nv_bfloat16 g_Whi[6 * 128 * 128];
__device__ __nv_bfloat16 g_Wlo[6 * 128 * 128];
__device__ float g_inv[NMAX];
__device__ int   g_rs [NMAX + 1];
__device__ int   g_csr[EMAX];
__device__ float g_G  [64 * 128];

// ---- fused: CSR build + prescale + layer-1 gather (csr kept in smem) + convW ----
// dynamic smem: sU [n_per*66 floats] | scsr [e_per ints]
__global__ void __launch_bounds__(512)
k_csrg(const int* __restrict__ ei, const float* __restrict__ x,
       __nv_bfloat16* __restrict__ Xhi, __nv_bfloat16* __restrict__ Xlo,
       int E, int n_per, int e_per, int B,
       const float* w0, const float* w1, const float* w2,
       const float* w3, const float* w4, const float* w5) {
    int blk = blockIdx.x, tid = threadIdx.x;
    if (blk >= B) {
        int b = blk - B;
        const float* srcs[6] = {w0, w1, w2, w3, w4, w5};
        const int Ks[6] = {64, 128, 128, 128, 128, 128};
        const float* W = srcs[b];
        int K = Ks[b];
        __nv_bfloat16* oh = g_Whi + b * 16384;
        __nv_bfloat16* ol = g_Wlo + b * 16384;
        for (int id = tid; id < 128 * K; id += 512) {
            int n = id / K, k = id % K;
            float v = W[k * 128 + n];             // transpose: Wt[n,k] = W[k,n]
            __nv_bfloat16 h = __float2bfloat16(v);
            oh[id] = h;
            ol[id] = __float2bfloat16(v - __bfloat162float(h));
        }
        return;
    }
    extern __shared__ float dyn[];
    float* sU = dyn;                              // [512][66]
    int* scsr = (int*)(dyn + n_per * 66);         // [e_per]
    __shared__ int cnt[512];
    __shared__ int off[512];
    __shared__ int sstart[512];
    __shared__ float sinv[512];
    int g = blk;
    int node0 = g * n_per;
    int ebase = g * e_per;
    int wid = tid >> 5, lane = tid & 31;

    cnt[tid] = 0;
    __syncthreads();
    for (int j = tid; j < e_per; j += 512)
        atomicAdd(&cnt[ei[E + ebase + j] - node0], 1);
    __syncthreads();
    int v = cnt[tid];
    off[tid] = v;
    __syncthreads();
#pragma unroll
    for (int s = 1; s < 512; s <<= 1) {
        int t = (tid >= s) ? off[tid - s] : 0;
        __syncthreads();
        off[tid] += t;
        __syncthreads();
    }
    int excl = off[tid] - v;
    float iv = rsqrtf((float)(v + 1));
    g_rs[node0 + tid] = ebase + excl;
    g_inv[node0 + tid] = iv;
    sinv[tid] = iv;
    sstart[tid] = excl;                           // local list start (off = end)
    if (tid == 511) g_rs[node0 + 512] = ebase + e_per;
    cnt[tid] = excl;                              // local cursor
    __syncthreads();
    for (int j = tid; j < e_per; j += 512) {
        int src = ei[ebase + j];
        int ld  = ei[E + ebase + j] - node0;
        int pos = atomicAdd(&cnt[ld], 1);
        scsr[pos] = src;
        g_csr[ebase + pos] = src;                 // global copy for later layers
    }
    // prescale into smem
    const float2* xg = (const float2*)x;
    size_t base2 = (size_t)node0 * 32;
    for (int i = tid; i < n_per * 32; i += 512) {
        int row = i >> 5, l = i & 31;
        float2 vv = xg[base2 + i];
        float s = sinv[row];
        vv.x *= s; vv.y *= s;
        ((float2*)sU)[row * 33 + l] = vv;
    }
    __syncthreads();

    // layer-1 gather: warp per node, lane = 2 dims; indices from smem scsr
    const float2* sU2 = (const float2*)sU;
    for (int nn = wid; nn < n_per; nn += 16) {
        float2 acc = sU2[nn * 33 + lane];         // self loop
        float2 acc2 = make_float2(0.f, 0.f);
        int s = sstart[nn], e = off[nn], j = s;
        for (; j + 1 < e; j += 2) {
            int a = scsr[j] - node0, b2 = scsr[j + 1] - node0;
            float2 v0 = sU2[a * 33 + lane], v1 = sU2[b2 * 33 + lane];
            acc.x += v0.x; acc.y += v0.y;
            acc2.x += v1.x; acc2.y += v1.y;
        }
        if (j < e) {
            float2 v0 = sU2[(scsr[j] - node0) * 33 + lane];
            acc.x += v0.x; acc.y += v0.y;
        }
        float ivn = sinv[nn];
        float ox = (acc.x + acc2.x) * ivn, oy = (acc.y + acc2.y) * ivn;
        __nv_bfloat16 hx = __float2bfloat16(ox), hy = __float2bfloat16(oy);
        __nv_bfloat162 hh; hh.x = hx; hh.y = hy;
        __nv_bfloat162 ll;
        ll.x = __float2bfloat16(ox - __bfloat162float(hx));
        ll.y = __float2bfloat16(oy - __bfloat162float(hy));
        ((__nv_bfloat162*)Xhi)[(size_t)(node0 + nn) * 32 + lane] = hh;
        ((__nv_bfloat162*)Xlo)[(size_t)(node0 + nn) * 32 + lane] = ll;
    }
}

// ---------------- mma helper ----------------
#define MMA16816(c, a, b0, b1)                                             \
    asm volatile("mma.sync.aligned.m16n8k16.row.col.f32.bf16.bf16.f32 "    \
        "{%0,%1,%2,%3}, {%4,%5,%6,%7}, {%8,%9}, {%0,%1,%2,%3};"            \
        : "+f"((c)[0]), "+f"((c)[1]), "+f"((c)[2]), "+f"((c)[3])           \
        : "r"((a)[0]), "r"((a)[1]), "r"((a)[2]), "r"((a)[3]),              \
          "r"(b0), "r"(b1))

// ---- full-width GEMM (R12): CTA 128M x 128N, warp m32 x n64 ---------------------
template <int K, int MODE>
__global__ void __launch_bounds__(256)
k_gemm_mma(const __nv_bfloat16* __restrict__ Xhi, const __nv_bfloat16* __restrict__ Xlo,
           const __nv_bfloat16* __restrict__ Whi, const __nv_bfloat16* __restrict__ Wlo,
           const float* __restrict__ bias, float* __restrict__ Y,
           __nv_bfloat16* __restrict__ Phi, __nv_bfloat16* __restrict__ Plo) {
    constexpr int KP = K + 8;
    extern __shared__ __nv_bfloat16 sB[];
    __nv_bfloat16* sBhi = sB;
    __nv_bfloat16* sBlo = sB + 128 * KP;

    int tid = threadIdx.x, wid = tid >> 5, lane = tid & 31;
    int q = lane & 3, g4 = lane >> 2;
    int m0 = blockIdx.x * 128 + (wid & 3) * 32;
    int nh = wid >> 2;

    for (int id = tid; id < 128 * (K / 8); id += 256) {
        int n = id / (K / 8), kb = (id % (K / 8)) * 8;
        *(float4*)&sBhi[n * KP + kb] = *(const float4*)(Whi + (size_t)n * K + kb);
        *(float4*)&sBlo[n * KP + kb] = *(const float4*)(Wlo + (size_t)n * K + kb);
    }
    __syncthreads();

    float c[2][8][4] = {};
    for (int kc = 0; kc < K / 16; kc++) {
        int k0 = kc * 16;
        uint32_t ah[2][4], al[2][4];
#pragma unroll
        for (int mh = 0; mh < 2; mh++) {
            size_t base = (size_t)(m0 + mh * 16 + g4) * K + k0 + q * 2;
            ah[mh][0] = *(const uint32_t*)(Xhi + base);
            ah[mh][1] = *(const uint32_t*)(Xhi + base + 8 * K);
            ah[mh][2] = *(const uint32_t*)(Xhi + base + 8);
            ah[mh][3] = *(const uint32_t*)(Xhi + base + 8 * K + 8);
            al[mh][0] = *(const uint32_t*)(Xlo + base);
            al[mh][1] = *(const uint32_t*)(Xlo + base + 8 * K);
            al[mh][2] = *(const uint32_t*)(Xlo + base + 8);
            al[mh][3] = *(const uint32_t*)(Xlo + base + 8 * K + 8);
        }
#pragma unroll
        for (int nc = 0; nc < 8; nc++) {
            int n = nh * 64 + nc * 8 + g4;
            const __nv_bfloat16* pb = &sBhi[n * KP + k0 + q * 2];
            const __nv_bfloat16* pl = &sBlo[n * KP + k0 + q * 2];
            uint32_t bh0 = *(const uint32_t*)pb, bh1 = *(const uint32_t*)(pb + 8);
            uint32_t bl0 = *(const uint32_t*)pl, bl1 = *(const uint32_t*)(pl + 8);
#pragma unroll
            for (int mh = 0; mh < 2; mh++) {
                MMA16816(c[mh][nc], ah[mh], bh0, bh1);
                MMA16816(c[mh][nc], ah[mh], bl0, bl1);
                MMA16816(c[mh][nc], al[mh], bh0, bh1);
            }
        }
    }

#pragma unroll
    for (int mh = 0; mh < 2; mh++) {
        int r0 = m0 + mh * 16 + g4;
        if (MODE == 0) {
            float s0 = g_inv[r0], s1 = g_inv[r0 + 8];
#pragma unroll
            for (int nc = 0; nc < 8; nc++) {
                int col = nh * 64 + nc * 8 + q * 2;
                *(float2*)(Y + (size_t)r0 * 128 + col) =
                    make_float2(c[mh][nc][0] * s0, c[mh][nc][1] * s0);
                *(float2*)(Y + (size_t)(r0 + 8) * 128 + col) =
                    make_float2(c[mh][nc][2] * s1, c[mh][nc][3] * s1);
            }
        } else {
#pragma unroll
            for (int nc = 0; nc < 8; nc++) {
                int col = nh * 64 + nc * 8 + q * 2;
                float b0 = __ldg(bias + col), b1 = __ldg(bias + col + 1);
                float t0 = fmaxf(c[mh][nc][0] + b0, 0.f);
                float t1 = fmaxf(c[mh][nc][1] + b1, 0.f);
                float t2 = fmaxf(c[mh][nc][2] + b0, 0.f);
                float t3 = fmaxf(c[mh][nc][3] + b1, 0.f);
                __nv_bfloat16 h0 = __float2bfloat16(t0), h1 = __float2bfloat16(t1);
                __nv_bfloat162 hh; hh.x = h0; hh.y = h1;
                __nv_bfloat162 ll;
                ll.x = __float2bfloat16(t0 - __bfloat162float(h0));
                ll.y = __float2bfloat16(t1 - __bfloat162float(h1));
                *(__nv_bfloat162*)(Phi + (size_t)r0 * 128 + col) = hh;
                *(__nv_bfloat162*)(Plo + (size_t)r0 * 128 + col) = ll;
                __nv_bfloat16 h2 = __float2bfloat16(t2), h3 = __float2bfloat16(t3);
                __nv_bfloat162 hh2; hh2.x = h2; hh2.y = h3;
                __nv_bfloat162 ll2;
                ll2.x = __float2bfloat16(t2 - __bfloat162float(h2));
                ll2.y = __float2bfloat16(t3 - __bfloat162float(h3));
                *(__nv_bfloat162*)(Phi + (size_t)(r0 + 8) * 128 + col) = hh2;
                *(__nv_bfloat162*)(Plo + (size_t)(r0 + 8) * 128 + col) = ll2;
            }
        }
    }
}

// ---- heads GEMM: grid = 3*gg. p=0 fused node head -> out; p=1/2 store A/Bm ------
__global__ void __launch_bounds__(256)
k_heads(const __nv_bfloat16* __restrict__ Xhi, const __nv_bfloat16* __restrict__ Xlo,
        const float* __restrict__ bn1, const float* __restrict__ wn2,
        const float* __restrict__ bn2, float* __restrict__ out, int MA,
        float* __restrict__ Ya, float* __restrict__ Yb, int gg) {
    constexpr int K = 128, KP = K + 8;
    extern __shared__ __nv_bfloat16 sB[];
    __nv_bfloat16* sBhi = sB;
    __nv_bfloat16* sBlo = sB + 128 * KP;
    __shared__ float slg[2][128][4];

    int p = blockIdx.x / gg;
    int mb = blockIdx.x - p * gg;
    const __nv_bfloat16* Whi = g_Whi + (3 + p) * 16384;
    const __nv_bfloat16* Wlo = g_Wlo + (3 + p) * 16384;

    int tid = threadIdx.x, wid = tid >> 5, lane = tid & 31;
    int q = lane & 3, g4 = lane >> 2;
    int m0 = mb * 128 + (wid & 3) * 32;
    int nh = wid >> 2;

    for (int id = tid; id < 128 * (K / 8); id += 256) {
        int n = id / (K / 8), kb = (id % (K / 8)) * 8;
        *(float4*)&sBhi[n * KP + kb] = *(const float4*)(Whi + (size_t)n * K + kb);
        *(float4*)&sBlo[n * KP + kb] = *(const float4*)(Wlo + (size_t)n * K + kb);
    }
    __syncthreads();

    float c[2][8][4] = {};
    for (int kc = 0; kc < K / 16; kc++) {
        int k0 = kc * 16;
        uint32_t ah[2][4], al[2][4];
#pragma unroll
        for (int mh = 0; mh < 2; mh++) {
            size_t base = (size_t)(m0 + mh * 16 + g4) * K + k0 + q * 2;
            ah[mh][0] = *(const uint32_t*)(Xhi + base);
            ah[mh][1] = *(const uint32_t*)(Xhi + base + 8 * K);
            ah[mh][2] = *(const uint32_t*)(Xhi + base + 8);
            ah[mh][3] = *(const uint32_t*)(Xhi + base + 8 * K + 8);
            al[mh][0] = *(const uint32_t*)(Xlo + base);
            al[mh][1] = *(const uint32_t*)(Xlo + base + 8 * K);
            al[mh][2] = *(const uint32_t*)(Xlo + base + 8);
            al[mh][3] = *(const uint32_t*)(Xlo + base + 8 * K + 8);
        }
#pragma unroll
        for (int nc = 0; nc < 8; nc++) {
            int n = nh * 64 + nc * 8 + g4;
            const __nv_bfloat16* pb = &sBhi[n * KP + k0 + q * 2];
            const __nv_bfloat16* pl = &sBlo[n * KP + k0 + q * 2];
            uint32_t bh0 = *(const uint32_t*)pb, bh1 = *(const uint32_t*)(pb + 8);
            uint32_t bl0 = *(const uint32_t*)pl, bl1 = *(const uint32_t*)(pl + 8);
#pragma unroll
            for (int mh = 0; mh < 2; mh++) {
                MMA16816(c[mh][nc], ah[mh], bh0, bh1);
                MMA16816(c[mh][nc], ah[mh], bl0, bl1);
                MMA16816(c[mh][nc], al[mh], bh0, bh1);
            }
        }
    }

    if (p != 0) {
        float* Y = (p == 1) ? Ya : Yb;
#pragma unroll
        for (int mh = 0; mh < 2; mh++) {
            int r0 = m0 + mh * 16 + g4;
#pragma unroll
            for (int nc = 0; nc < 8; nc++) {
                int col = nh * 64 + nc * 8 + q * 2;
                *(float2*)(Y + (size_t)r0 * 128 + col) =
                    make_float2(c[mh][nc][0], c[mh][nc][1]);
                *(float2*)(Y + (size_t)(r0 + 8) * 128 + col) =
                    make_float2(c[mh][nc][2], c[mh][nc][3]);
            }
        }
        return;
    }
    float lg[4][4] = {};
#pragma unroll
    for (int mh = 0; mh < 2; mh++) {
#pragma unroll
        for (int nc = 0; nc < 8; nc++) {
            int col = nh * 64 + nc * 8 + q * 2;
            float b0 = __ldg(bn1 + col), b1 = __ldg(bn1 + col + 1);
            float4 w0 = __ldg((const float4*)wn2 + col);
            float4 w1 = __ldg((const float4*)wn2 + col + 1);
            float t0 = fmaxf(c[mh][nc][0] + b0, 0.f);
            float t1 = fmaxf(c[mh][nc][1] + b1, 0.f);
            float t2 = fmaxf(c[mh][nc][2] + b0, 0.f);
            float t3 = fmaxf(c[mh][nc][3] + b1, 0.f);
            int ra = mh * 2, rb = mh * 2 + 1;
            lg[ra][0] += t0 * w0.x + t1 * w1.x;
            lg[ra][1] += t0 * w0.y + t1 * w1.y;
            lg[ra][2] += t0 * w0.z + t1 * w1.z;
            lg[ra][3] += t0 * w0.w + t1 * w1.w;
            lg[rb][0] += t2 * w0.x + t3 * w1.x;
            lg[rb][1] += t2 * w0.y + t3 * w1.y;
            lg[rb][2] += t2 * w0.z + t3 * w1.z;
            lg[rb][3] += t2 * w0.w + t3 * w1.w;
        }
    }
#pragma unroll
    for (int i = 0; i < 4; i++)
#pragma unroll
        for (int a = 0; a < 4; a++) {
            lg[i][a] += __shfl_xor_sync(0xffffffffu, lg[i][a], 1);
            lg[i][a] += __shfl_xor_sync(0xffffffffu, lg[i][a], 2);
        }
    if (q == 0) {
        int lr0 = (wid & 3) * 32 + g4;
#pragma unroll
        for (int i = 0; i < 4; i++) {
            int lr = lr0 + ((i & 1) ? 8 : 0) + ((i >> 1) ? 16 : 0);
#pragma unroll
            for (int a = 0; a < 4; a++) slg[nh][lr][a] = lg[i][a];
        }
    }
    __syncthreads();
    for (int id = tid; id < 512; id += 256) {
        int lr = id >> 2, a = id & 3;
        int R = mb * 128 + lr;
        int g = R >> 9, ln = R & 511;
        out[(size_t)g * MA + ln * 4 + a] =
            slg[0][lr][a] + slg[1][lr][a] + __ldg(bn2 + a);
    }
}

// ---- GCN aggregation (layers 2/3): block=(g, half), csr staged in smem -----------
// dynamic smem: sU [n_per*66 floats] | scsr [e_per ints]
__global__ void __launch_bounds__(512)
k_gatherh(const float* __restrict__ U, const float* __restrict__ bias,
          __nv_bfloat16* __restrict__ Hhi, __nv_bfloat16* __restrict__ Hlo,
          int n_per, int e_per, float* __restrict__ Gout) {
    extern __shared__ float dyn[];
    float* sU = dyn;                              // float2 [512][33]
    int* scsr = (int*)(dyn + n_per * 66);         // [e_per]
    __shared__ float spool[16][66];
    int b = blockIdx.x;
    int g = b >> 1, hh = b & 1;
    int qd = hh * 64;
    int tid = threadIdx.x, wid = tid >> 5, lane = tid & 31;
    int node0 = g * n_per;
    int ebase = g * e_per;

    for (int i = tid; i < n_per * 32; i += 512) {
        int row = i >> 5, l = i & 31;
        ((float2*)sU)[row * 33 + l] =
            *(const float2*)(U + (size_t)(node0 + row) * 128 + qd + 2 * l);
    }
    for (int j = tid; j < e_per; j += 512)
        scsr[j] = g_csr[ebase + j] - node0;       // localized indices
    __syncthreads();

    const float2* sU2 = (const float2*)sU;
    float2 bb = *(const float2*)(bias + qd + 2 * lane);
    float px = 0.f, py = 0.f;
    for (int nn = wid; nn < n_per; nn += 16) {
        float2 a0 = sU2[nn * 33 + lane];          // self loop
        float2 a1 = make_float2(0.f, 0.f);
        float2 a2 = make_float2(0.f, 0.f);
        float2 a3 = make_float2(0.f, 0.f);
        int s = g_rs[node0 + nn] - ebase, e = g_rs[node0 + nn + 1] - ebase, j = s;
        for (; j + 3 < e; j += 4) {
            int i0 = scsr[j], i1 = scsr[j + 1], i2 = scsr[j + 2], i3 = scsr[j + 3];
            float2 v0 = sU2[i0 * 33 + lane];
            float2 v1 = sU2[i1 * 33 + lane];
            float2 v2 = sU2[i2 * 33 + lane];
            float2 v3 = sU2[i3 * 33 + lane];
            a0.x += v0.x; a0.y += v0.y;
            a1.x += v1.x; a1.y += v1.y;
            a2.x += v2.x; a2.y += v2.y;
            a3.x += v3.x; a3.y += v3.y;
        }
        for (; j < e; j++) {
            float2 v0 = sU2[scsr[j] * 33 + lane];
            a0.x += v0.x; a0.y += v0.y;
        }
        float iv = g_inv[node0 + nn];
        float sx = (a0.x + a1.x) + (a2.x + a3.x);
        float sy = (a0.y + a1.y) + (a2.y + a3.y);
        float ox = fmaxf(fmaf(sx, iv, bb.x), 0.f);
        float oy = fmaxf(fmaf(sy, iv, bb.y), 0.f);
        px += ox; py += oy;
        __nv_bfloat16 hx = __float2bfloat16(ox), hy = __float2bfloat16(oy);
        __nv_bfloat162 hv; hv.x = hx; hv.y = hy;
        __nv_bfloat162 lv;
        lv.x = __float2bfloat16(ox - __bfloat162float(hx));
        lv.y = __float2bfloat16(oy - __bfloat162float(hy));
        ((__nv_bfloat162*)Hhi)[(size_t)(node0 + nn) * 64 + qd / 2 + lane] = hv;
        ((__nv_bfloat162*)Hlo)[(size_t)(node0 + nn) * 64 + qd / 2 + lane] = lv;
    }
    if (Gout != nullptr) {
        spool[wid][2 * lane]     = px;
        spool[wid][2 * lane + 1] = py;
        __syncthreads();
        if (tid < 64) {
            float s = 0.f;
#pragma unroll
            for (int w = 0; w < 16; w++) s += spool[w][tid];
            Gout[g * 128 + qd + tid] = s / (float)n_per;
        }
    }
}

// ---- edge head + value head merged (R12) ----------------------------------------
#define EQ_STRIDE 36
__global__ void __launch_bounds__(512)
k_edgev(const float* __restrict__ A, const float* __restrict__ Bm,
        const int* __restrict__ ei, const float* __restrict__ be1,
        const float* __restrict__ we2, const float* __restrict__ be2,
        float* __restrict__ out, int E, int n_per, int e_per, int MA, int nblk,
        int B, const float* __restrict__ wv1, const float* __restrict__ bv1,
        const float* __restrict__ wv2, const float* __restrict__ bv2, int voff) {
    extern __shared__ float sm[];
    int b = blockIdx.x;
    int tid = threadIdx.x;
    if (b >= 2 * B) {
        int g = b - 2 * B;
        float* gs  = sm;
        float* red = sm + 128;
        if (tid < 128) gs[tid] = g_G[g * 128 + tid];
        __syncthreads();
        if (tid < 128) {
            float acc = bv1[tid];
#pragma unroll
            for (int k = 0; k < 128; k++) acc = fmaf(gs[k], wv1[k * 128 + tid], acc);
            red[tid] = fmaxf(acc, 0.f) * wv2[tid];
        }
        __syncthreads();
        for (int off = 64; off; off >>= 1) {
            if (tid < off) red[tid] += red[tid + off];
            __syncthreads();
        }
        if (tid == 0) out[voff + g] = red[0] + bv2[0];
        return;
    }
    float* sA = sm;
    float* sB = sm + n_per * EQ_STRIDE;
    __shared__ float swb[32][4];
    int g = b >> 1, eh = b & 1;
    int node0 = g * n_per;
    int ehalf = e_per >> 1;
    int e0 = g * e_per + eh * ehalf;

    int srcs[8], dsts[8];
#pragma unroll
    for (int j = 0; j < 8; j++) {
        int ge = e0 + tid + j * 512;
        srcs[j] = (ei[ge] - node0) * EQ_STRIDE;
        dsts[j] = (ei[E + ge] - node0) * EQ_STRIDE;
    }
    float p0[8], p1[8];
#pragma unroll
    for (int j = 0; j < 8; j++) { p0[j] = 0.f; p1[j] = 0.f; }

    for (int q = 0; q < 4; q++) {
        int qd = q * 32;
        __syncthreads();
        for (int i = tid; i < n_per * 8; i += 512) {
            int row = i >> 3, c = (i & 7) << 2;
            *(float4*)&sA[row * EQ_STRIDE + c] =
                *(const float4*)(A + (size_t)(node0 + row) * 128 + qd + c);
            *(float4*)&sB[row * EQ_STRIDE + c] =
                *(const float4*)(Bm + (size_t)(node0 + row) * 128 + qd + c);
        }
        if (tid < 32) {
            swb[tid][0] = we2[(qd + tid) * 2];
            swb[tid][1] = we2[(qd + tid) * 2 + 1];
            swb[tid][2] = be1[qd + tid];
        }
        __syncthreads();
#pragma unroll
        for (int j = 0; j < 8; j++) {
            int s = srcs[j], dd = dsts[j];
            float a0 = p0[j], a1 = p1[j];
#pragma unroll
            for (int d = 0; d < 32; d += 4) {
                float4 a4 = *(const float4*)&sA[s + d];
                float4 b4 = *(const float4*)&sB[dd + d];
                float t;
                t = fmaxf(a4.x + b4.x + swb[d][2], 0.f);
                a0 += t * swb[d][0]; a1 += t * swb[d][1];
                t = fmaxf(a4.y + b4.y + swb[d + 1][2], 0.f);
                a0 += t * swb[d + 1][0]; a1 += t * swb[d + 1][1];
                t = fmaxf(a4.z + b4.z + swb[d + 2][2], 0.f);
                a0 += t * swb[d + 2][0]; a1 += t * swb[d + 2][1];
                t = fmaxf(a4.w + b4.w + swb[d + 3][2], 0.f);
                a0 += t * swb[d + 3][0]; a1 += t * swb[d + 3][1];
            }
            p0[j] = a0; p1[j] = a1;
        }
    }
    float bb0 = __ldg(be2), bb1 = __ldg(be2 + 1);
    size_t obase = (size_t)g * MA + nblk;
    int le0 = eh * ehalf;
#pragma unroll
    for (int j = 0; j < 8; j++) {
        int le = le0 + tid + j * 512;
        *(float2*)&out[obase + (size_t)le * 2] = make_float2(p0[j] + bb0, p1[j] + bb1);
    }
}

// ---------------- launch ----------------
extern "C" void kernel_launch(void* const* d_in, const int* in_sizes, int n_in,
                              void* d_out, int out_size) {
    const float* x  = (const float*)d_in[0];
    const int*   ei = (const int*)d_in[1];
    int N = in_sizes[0] / 64;
    int E = in_sizes[1] / 2;

    int wb = n_in - 18;
    const float* w_g1 = (const float*)d_in[wb + 0];
    const float* b_g1 = (const float*)d_in[wb + 1];
    const float* w_g2 = (const float*)d_in[wb + 2];
    const float* b_g2 = (const float*)d_in[wb + 3];
    const float* w_g3 = (const float*)d_in[wb + 4];
    const float* b_g3 = (const float*)d_in[wb + 5];
    const float* wn1  = (const float*)d_in[wb + 6];
    const float* bn1  = (const float*)d_in[wb + 7];
    const float* wn2  = (const float*)d_in[wb + 8];
    const float* bn2  = (const float*)d_in[wb + 9];
    const float* we1  = (const float*)d_in[wb + 10];
    const float* be1  = (const float*)d_in[wb + 11];
    const float* we2  = (const float*)d_in[wb + 12];
    const float* be2  = (const float*)d_in[wb + 13];
    const float* wv1  = (const float*)d_in[wb + 14];
    const float* bv1  = (const float*)d_in[wb + 15];
    const float* wv2  = (const float*)d_in[wb + 16];
    const float* bv2  = (const float*)d_in[wb + 17];

    const int n_per = 512;
    int B     = N / n_per;
    int e_per = E / B;
    int MA    = n_per * 4 + e_per * 2;
    int voff  = out_size - B;
    float* out = (float*)d_out;

    float *U, *A, *Bm, *G;
    __nv_bfloat16 *Hhi, *Hlo, *Xhi, *Xlo, *Whi, *Wlo;
    cudaGetSymbolAddress((void**)&U,   g_U);
    cudaGetSymbolAddress((void**)&A,   g_A);
    cudaGetSymbolAddress((void**)&Bm,  g_B);
    cudaGetSymbolAddress((void**)&G,   g_G);
    cudaGetSymbolAddress((void**)&Hhi, g_Hhi);
    cudaGetSymbolAddress((void**)&Hlo, g_Hlo);
    cudaGetSymbolAddress((void**)&Xhi, g_Xhi);
    cudaGetSymbolAddress((void**)&Xlo, g_Xlo);
    cudaGetSymbolAddress((void**)&Whi, g_Whi);
    cudaGetSymbolAddress((void**)&Wlo, g_Wlo);

    const int SM64  = 2 * 128 * (64 + 8)  * 2;     // 36,864 B
    const int SM128 = 2 * 128 * (128 + 8) * 2;     // 69,632 B
    const int SMEQ  = n_per * EQ_STRIDE * 4 * 2;   // 147,456 B
    const int SMGF  = n_per * 66 * 4 + e_per * 4;  // 135,168 + 32,768 = 167,936 B
    cudaFuncSetAttribute(k_csrg,             cudaFuncAttributeMaxDynamicSharedMemorySize, SMGF);
    cudaFuncSetAttribute(k_gemm_mma<64, 3>,  cudaFuncAttributeMaxDynamicSharedMemorySize, SM64);
    cudaFuncSetAttribute(k_gemm_mma<128, 0>, cudaFuncAttributeMaxDynamicSharedMemorySize, SM128);
    cudaFuncSetAttribute(k_heads,            cudaFuncAttributeMaxDynamicSharedMemorySize, SM128);
    cudaFuncSetAttribute(k_edgev,            cudaFuncAttributeMaxDynamicSharedMemorySize, SMEQ);
    cudaFuncSetAttribute(k_gatherh,          cudaFuncAttributeMaxDynamicSharedMemorySize, SMGF);

    int gg = N / 128;

    // (1) fused CSR build + prescale(smem) + layer-1 gather (smem csr) + convW
    k_csrg<<<B + 6, 512, SMGF>>>(ei, x, Xhi, Xlo, E, n_per, e_per, B,
                                 w_g1, w_g2, w_g3, wn1, we1, we1 + 128 * 128);
    // (2) layer-1 GEMM
    k_gemm_mma<64, 3><<<gg, 256, SM64>>>(Xhi, Xlo, Whi + 0 * 16384, Wlo + 0 * 16384,
                                         b_g1, nullptr, Hhi, Hlo);
    // layer 2
    k_gemm_mma<128, 0><<<gg, 256, SM128>>>(Hhi, Hlo, Whi + 1 * 16384, Wlo + 1 * 16384,
                                           nullptr, U, nullptr, nullptr);
    k_gatherh<<<B * 2, 512, SMGF>>>(U, b_g2, Hhi, Hlo, n_per, e_per, nullptr);
    // layer 3 (+ fused mean pool)
    k_gemm_mma<128, 0><<<gg, 256, SM128>>>(Hhi, Hlo, Whi + 2 * 16384, Wlo + 2 * 16384,
                                           nullptr, U, nullptr, nullptr);
    k_gatherh<<<B * 2, 512, SMGF>>>(U, b_g3, Hhi, Hlo, n_per, e_per, G);

    // heads: node (fused) + edge A + edge Bm in one launch
    k_heads<<<3 * gg, 256, SM128>>>(Hhi, Hlo, bn1, wn2, bn2, out, MA, A, Bm, gg);

    // edge head + value head in one launch
    k_edgev<<<B * 2 + B, 512, SMEQ>>>(A, Bm, ei, be1, we2, be2, out,
                                      E, n_per, e_per, MA, n_per * 4,
                                      B, wv1, bv1, wv2, bv2, voff);
}